// round 12
// baseline (speedup 1.0000x reference)
#include <cuda_runtime.h>
#include <cstdint>

#define N_NODES 50000
#define N_EDGES 800000
#define HID 128

// ---------------- scratch ----------------
__device__ float    g_h  [N_NODES*HID];
__device__ float    g_agg[N_NODES*HID];
__device__ float    g_An [N_NODES*HID];
__device__ float    g_Bn [N_NODES*HID];
__device__ int      g_cntfill[2*N_NODES];      // [cnt | fill]
__device__ int      g_rowptr[N_NODES+1];
__device__ int      g_csr [N_EDGES];           // src per CSR position
__device__ int      g_csrE[N_EDGES];           // original edge id per CSR position
__device__ int      g_csrD[N_EDGES];           // dst per CSR position
__device__ uint32_t g_Wt [4*HID*256];          // tf32 [l][n][k] combined Wl|Wr
__device__ uint32_t g_W1s[2*HID*HID];          // tf32 [slice][n][k] from W1
__device__ uint32_t g_W2u[HID*64];             // tf32 [k][c] W2 transposed
__device__ float    g_W1c[8*HID];              // fp32 W1 cols 256..263 transposed

// ---------------- tf32 mma helpers ----------------
__device__ __forceinline__ uint32_t f2tf(float f){
    uint32_t r;
    asm("cvt.rna.tf32.f32 %0, %1;" : "=r"(r) : "f"(f));
    return r;
}
__device__ __forceinline__ void mma_tf32(float* c, const uint32_t* a, uint32_t b0, uint32_t b1){
    asm volatile("mma.sync.aligned.m16n8k8.row.col.f32.tf32.tf32.f32 "
        "{%0,%1,%2,%3}, {%4,%5,%6,%7}, {%8,%9}, {%0,%1,%2,%3};"
        : "+f"(c[0]), "+f"(c[1]), "+f"(c[2]), "+f"(c[3])
        : "r"(a[0]), "r"(a[1]), "r"(a[2]), "r"(a[3]), "r"(b0), "r"(b1));
}

// ---------------- combo: weight prep + hist + input projection ----------------
#define PB 512                           // prep blocks (4*128*256/256)
#define EB ((N_EDGES+255)/256)           // 3125
#define NB ((N_NODES+1)/2)               // 25000

__global__ void prep_hist_inproj_k(const int* __restrict__ dst, const float* __restrict__ x,
                                   const float* __restrict__ Win, const float* __restrict__ bin,
                                   const float* __restrict__ W1, const float* __restrict__ W2,
                                   const float* __restrict__ Wl, const float* __restrict__ Wr){
    if(blockIdx.x < PB){
        int i = blockIdx.x*256 + threadIdx.x;
        if(i < 4*HID*256){
            int l = i >> 15; int r = i & 32767; int n = r >> 8, k = r & 255;
            float v = (k < 128) ? Wl[l*16384 + n*128 + k] : Wr[l*16384 + n*128 + (k-128)];
            g_Wt[i] = f2tf(v);
        }
        if(i < 2*HID*HID){
            int s = i >> 14; int r = i & 16383; int n = r >> 7, k = r & 127;
            g_W1s[i] = f2tf(W1[n*264 + s*128 + k]);
        }
        if(i < HID*64){ int k = i/64, c = i%64; g_W2u[i] = f2tf(W2[c*HID + k]); }
        if(i < 8*HID) { int k = i/HID, c = i%HID; g_W1c[i] = W1[c*264 + 256 + k]; }
        return;
    }
    if(blockIdx.x < PB + EB){
        int i = (blockIdx.x - PB)*256 + threadIdx.x;
        if(i < N_EDGES) atomicAdd(&g_cntfill[dst[i]], 1);
        return;
    }
    __shared__ float xs[2][16];
    int tid = threadIdx.x;
    int n0 = (blockIdx.x - PB - EB)*2;
    if(tid < 32){
        int nn = tid/16, k = tid%16;
        int n = n0 + nn;
        xs[nn][k] = (n < N_NODES) ? x[n*16 + k] : 0.f;
    }
    __syncthreads();
    int nn = tid/HID, c = tid%HID;
    int n = n0 + nn;
    if(n < N_NODES){
        float acc = bin[c];
        const float* w = Win + c*16;
        #pragma unroll
        for(int k = 0; k < 16; k++) acc += xs[nn][k]*w[k];
        g_h[n*HID + c] = acc;
    }
}

// ---------------- fast scan ----------------
#define SCH 49   // ceil(50000/1024)

__global__ void scan_k(){
    __shared__ int ssum[1024];
    int tid = threadIdx.x;
    int base = tid*SCH;
    int v[SCH];
    int tot = 0;
    #pragma unroll
    for(int j = 0; j < SCH; j++){
        int i = base + j;
        v[j] = (i < N_NODES) ? g_cntfill[i] : 0;
        tot += v[j];
    }
    ssum[tid] = tot;
    __syncthreads();
    for(int off = 1; off < 1024; off <<= 1){
        int t = (tid >= off) ? ssum[tid-off] : 0;
        __syncthreads();
        ssum[tid] += t;
        __syncthreads();
    }
    int run = ssum[tid] - tot;
    #pragma unroll
    for(int j = 0; j < SCH; j++){
        int i = base + j;
        if(i < N_NODES) g_rowptr[i] = run;
        run += v[j];
    }
    if(tid == 1023) g_rowptr[N_NODES] = run;
}

__global__ void fill_k(const int* __restrict__ src, const int* __restrict__ dst){
    int i = blockIdx.x*blockDim.x + threadIdx.x;
    if(i < N_EDGES){
        int d = dst[i];
        int pos = g_rowptr[d] + atomicAdd(&g_cntfill[N_NODES + d], 1);
        g_csr [pos] = src[i];
        g_csrE[pos] = i;
        g_csrD[pos] = d;
    }
}

// ---------------- mean aggregation (CSR gather, MLP=4) + cntfill re-zero ----------------
__global__ void agg_k(){
    // reset histogram/fill counters for the NEXT graph replay (runs after fill_k)
    int z = blockIdx.x*blockDim.x + threadIdx.x;
    if(z < 2*N_NODES) g_cntfill[z] = 0;

    int warp = threadIdx.x >> 5, lane = threadIdx.x & 31;
    int n = blockIdx.x*8 + warp;
    if(n >= N_NODES) return;
    int beg = g_rowptr[n], end = g_rowptr[n+1];
    float4 acc = make_float4(0.f,0.f,0.f,0.f);
    const float4* hp = reinterpret_cast<const float4*>(g_h);
    int j = beg;
    for(; j + 4 <= end; j += 4){
        int s0 = g_csr[j], s1 = g_csr[j+1], s2 = g_csr[j+2], s3 = g_csr[j+3];
        float4 v0 = hp[s0*32 + lane];
        float4 v1 = hp[s1*32 + lane];
        float4 v2 = hp[s2*32 + lane];
        float4 v3 = hp[s3*32 + lane];
        acc.x += (v0.x+v1.x) + (v2.x+v3.x);
        acc.y += (v0.y+v1.y) + (v2.y+v3.y);
        acc.z += (v0.z+v1.z) + (v2.z+v3.z);
        acc.w += (v0.w+v1.w) + (v2.w+v3.w);
    }
    for(; j < end; j++){
        int s = g_csr[j];
        float4 v = hp[s*32 + lane];
        acc.x += v.x; acc.y += v.y; acc.z += v.z; acc.w += v.w;
    }
    float inv = (end > beg) ? 1.0f/(float)(end - beg) : 0.0f;
    acc.x *= inv; acc.y *= inv; acc.z *= inv; acc.w *= inv;
    reinterpret_cast<float4*>(g_agg)[n*32 + lane] = acc;
}

// ---------------- layer GEMM (K=256, double-buffered) + bias/LN/ReLU; FUSE=1 emits An/Bn ----------------
// u32 offsets: A0=0 | B0 | A1 | B1 | PRM | PS | PQ | BS2(FUSE only)
// Hs (FUSE) aliases A0..B1 region (16896 u32 < 18432 u32).
#define GL_A0   0
#define GL_B0   4608
#define GL_A1   9216
#define GL_B1   13824
#define GL_PRM  18432
#define GL_PS   18816
#define GL_PQ   19072
#define GL_BS2  19328
#define GL_SMEM0 (GL_BS2*4)                 // 77312 B
#define GL_SMEM1 ((GL_BS2 + 4608)*4)        // 95744 B

template<int FUSE>
__global__ void __launch_bounds__(256) gemm_layer(
        const uint32_t* __restrict__ Wt,
        const float* __restrict__ bias, const float* __restrict__ lng,
        const float* __restrict__ lnb){
    extern __shared__ uint32_t smu[];
    uint32_t* Abuf[2] = {smu + GL_A0, smu + GL_A1};
    uint32_t* Bbuf[2] = {smu + GL_B0, smu + GL_B1};
    float* prm = (float*)(smu + GL_PRM);
    float* ps  = (float*)(smu + GL_PS);
    float* pq  = (float*)(smu + GL_PQ);
    uint32_t* Hs  = smu;                 // FUSE epilogue (aliases dead buffers)
    uint32_t* Bs2 = smu + GL_BS2;        // FUSE B staging

    int tid = threadIdx.x;
    int lane = tid & 31, wid = tid >> 5;
    int g = lane >> 2, t = lane & 3;
    int wy = wid & 3, wx = wid >> 2;
    int m0 = blockIdx.x*128;

    float c[2][8][4];
    #pragma unroll
    for(int mi = 0; mi < 2; mi++)
        #pragma unroll
        for(int nf = 0; nf < 8; nf++)
            #pragma unroll
            for(int j = 0; j < 4; j++) c[mi][nf][j] = 0.f;

    if(tid < 128){
        prm[tid] = bias[tid]; prm[128+tid] = lng[tid]; prm[256+tid] = lnb[tid];
    }

    int ldr = tid >> 3, ldc = (tid & 7)*4;         // each thread: rows ldr+{0,32,64,96}? no: s-index pattern
    float4 sa[4]; uint4 sb[4];

    // helper lambdas via macros: load chunk regs / store regs to buffer
    #define GL_LOAD(nc) do{ \
        const float* Ap = ((nc) < 4) ? g_agg : g_h; \
        int kc = ((nc) & 3)*32; \
        _Pragma("unroll") \
        for(int i = 0; i < 4; i++){ \
            int s = tid + i*256; \
            int r = s >> 3, c4 = (s & 7)*4; \
            int mr = m0 + r; if(mr >= N_NODES) mr = N_NODES-1; \
            sa[i] = *(const float4*)(Ap + mr*128 + kc + c4); \
            sb[i] = *(const uint4*)(Wt + r*256 + (nc)*32 + c4); \
        } \
    }while(0)

    #define GL_STORE(buf) do{ \
        uint32_t* Ad = Abuf[buf]; uint32_t* Bd = Bbuf[buf]; \
        _Pragma("unroll") \
        for(int i = 0; i < 4; i++){ \
            int s = tid + i*256; \
            int r = s >> 3, c4 = (s & 7)*4; \
            uint32_t* d = Ad + r*36 + c4; \
            d[0] = f2tf(sa[i].x); d[1] = f2tf(sa[i].y); d[2] = f2tf(sa[i].z); d[3] = f2tf(sa[i].w); \
            *(uint4*)(Bd + r*36 + c4) = sb[i]; \
        } \
    }while(0)

    (void)ldr; (void)ldc;
    GL_LOAD(0);
    GL_STORE(0);
    GL_LOAD(1);
    __syncthreads();

    for(int ch = 0; ch < 8; ch++){
        if(ch + 1 < 8){
            GL_STORE((ch+1)&1);          // regs hold chunk ch+1
            if(ch + 2 < 8) GL_LOAD(ch+2);
        }
        const uint32_t* a_sm = Abuf[ch&1] + (wy*32 + g)*36 + t;
        const uint32_t* b_sm = Bbuf[ch&1] + (wx*64 + g)*36 + t;
        #pragma unroll
        for(int kk = 0; kk < 4; kk++){
            int k0 = kk*8;
            uint32_t a[2][4];
            #pragma unroll
            for(int mi = 0; mi < 2; mi++){
                const uint32_t* p = a_sm + mi*16*36 + k0;
                a[mi][0] = p[0]; a[mi][1] = p[8*36]; a[mi][2] = p[4]; a[mi][3] = p[8*36+4];
            }
            #pragma unroll
            for(int nf = 0; nf < 8; nf++){
                const uint32_t* q = b_sm + nf*8*36 + k0;
                uint32_t b0 = q[0], b1 = q[4];
                mma_tf32(c[0][nf], a[0], b0, b1);
                mma_tf32(c[1][nf], a[1], b0, b1);
            }
        }
        __syncthreads();
    }
    #undef GL_LOAD
    #undef GL_STORE

    int colb = wx*64;
    #pragma unroll
    for(int mi = 0; mi < 2; mi++)
        #pragma unroll
        for(int rr = 0; rr < 2; rr++){
            float s = 0.f, sq = 0.f;
            #pragma unroll
            for(int nf = 0; nf < 8; nf++)
                #pragma unroll
                for(int j = 0; j < 2; j++){
                    int col = colb + nf*8 + 2*t + j;
                    float v = c[mi][nf][rr*2+j] + prm[col];
                    c[mi][nf][rr*2+j] = v;
                    s += v; sq += v*v;
                }
            s  += __shfl_xor_sync(0xffffffffu, s, 1);
            s  += __shfl_xor_sync(0xffffffffu, s, 2);
            sq += __shfl_xor_sync(0xffffffffu, sq, 1);
            sq += __shfl_xor_sync(0xffffffffu, sq, 2);
            if(t == 0){
                int row = wy*32 + mi*16 + rr*8 + g;
                ps[wx*128 + row] = s;
                pq[wx*128 + row] = sq;
            }
        }
    __syncthreads();
    #pragma unroll
    for(int mi = 0; mi < 2; mi++)
        #pragma unroll
        for(int rr = 0; rr < 2; rr++){
            int row = wy*32 + mi*16 + rr*8 + g;
            int m = m0 + row;
            float st  = ps[row] + ps[128+row];
            float sqt = pq[row] + pq[128+row];
            float mu  = st * (1.0f/128.0f);
            float var = sqt * (1.0f/128.0f) - mu*mu;
            float rs  = rsqrtf(var + 1e-5f);
            #pragma unroll
            for(int nf = 0; nf < 8; nf++){
                int col = colb + nf*8 + 2*t;
                float2 o;
                o.x = fmaxf((c[mi][nf][rr*2+0]-mu)*rs*prm[128+col]   + prm[256+col],   0.f);
                o.y = fmaxf((c[mi][nf][rr*2+1]-mu)*rs*prm[128+col+1] + prm[256+col+1], 0.f);
                if(m < N_NODES) *(float2*)(g_h + m*128 + col) = o;
                if(FUSE){
                    Hs[row*132 + col]   = f2tf(o.x);
                    Hs[row*132 + col+1] = f2tf(o.y);
                }
            }
        }

    if(FUSE){
        __syncthreads();
        #pragma unroll
        for(int sl = 0; sl < 2; sl++){
            const uint32_t* W = g_W1s + sl*16384;
            #pragma unroll
            for(int mi = 0; mi < 2; mi++)
                #pragma unroll
                for(int nf = 0; nf < 8; nf++)
                    #pragma unroll
                    for(int j = 0; j < 4; j++) c[mi][nf][j] = 0.f;

            uint4 sb2[4];
            #pragma unroll
            for(int i = 0; i < 4; i++){
                int s = tid + i*256;
                int r = s >> 3, c4 = (s & 7)*4;
                sb2[i] = *(const uint4*)(W + r*128 + c4);
            }
            for(int ch = 0; ch < 4; ch++){
                #pragma unroll
                for(int i = 0; i < 4; i++){
                    int s = tid + i*256;
                    int r = s >> 3, c4 = (s & 7)*4;
                    *(uint4*)(Bs2 + r*36 + c4) = sb2[i];
                }
                __syncthreads();
                if(ch + 1 < 4){
                    int nc = ch + 1;
                    #pragma unroll
                    for(int i = 0; i < 4; i++){
                        int s = tid + i*256;
                        int r = s >> 3, c4 = (s & 7)*4;
                        sb2[i] = *(const uint4*)(W + r*128 + nc*32 + c4);
                    }
                }
                const uint32_t* a_sm = Hs + (wy*32 + g)*132 + ch*32 + t;
                const uint32_t* b_sm = Bs2 + (wx*64 + g)*36 + t;
                #pragma unroll
                for(int kk = 0; kk < 4; kk++){
                    int k0 = kk*8;
                    uint32_t a[2][4];
                    #pragma unroll
                    for(int mi = 0; mi < 2; mi++){
                        const uint32_t* p = a_sm + mi*16*132 + k0;
                        a[mi][0] = p[0]; a[mi][1] = p[8*132]; a[mi][2] = p[4]; a[mi][3] = p[8*132+4];
                    }
                    #pragma unroll
                    for(int nf = 0; nf < 8; nf++){
                        const uint32_t* q = b_sm + nf*8*36 + k0;
                        uint32_t b0 = q[0], b1 = q[4];
                        mma_tf32(c[0][nf], a[0], b0, b1);
                        mma_tf32(c[1][nf], a[1], b0, b1);
                    }
                }
                __syncthreads();
            }
            float* out = sl ? g_Bn : g_An;
            #pragma unroll
            for(int mi = 0; mi < 2; mi++)
                #pragma unroll
                for(int rr = 0; rr < 2; rr++){
                    int row = wy*32 + mi*16 + rr*8 + g;
                    int m = m0 + row;
                    if(m < N_NODES){
                        #pragma unroll
                        for(int nf = 0; nf < 8; nf++){
                            int col = colb + nf*8 + 2*t;
                            *(float2*)(out + m*128 + col) =
                                make_float2(c[mi][nf][rr*2+0], c[mi][nf][rr*2+1]);
                        }
                    }
                }
        }
    }
}

// ---------------- edge head: CSR-order, warp-pipelined, 4x16 register-blocked phase 1 ----------------
#define EG 4
#define EPB (128*EG)
#define EH_H1_STRIDE 132
#define EH_W2_STRIDE 72
#define EH_F_H1   0
#define EH_F_W2   (EH_F_H1 + 128*EH_H1_STRIDE)
#define EH_F_W1C  (EH_F_W2 + 128*EH_W2_STRIDE)
#define EH_F_B1   (EH_F_W1C + 8*128)
#define EH_F_B2   (EH_F_B1 + 128)
#define EH_F_W3   (EH_F_B2 + 64)
#define EH_F_EAS  (EH_F_W3 + 64)          // [8 warps][128] floats
#define EH_F_IDS  (EH_F_EAS + 8*128)      // [8 warps][48] ints (eid|src|dst x16)
#define EH_F_END  (EH_F_IDS + 8*48)
#define EH_SMEM_BYTES (EH_F_END*4 + 64)

__global__ void __launch_bounds__(256) edge_k(
        const float* __restrict__ ea,
        const float* __restrict__ b1, const float* __restrict__ b2,
        const float* __restrict__ W3, const float* __restrict__ b3,
        float* __restrict__ out){
    extern __shared__ float smf[];
    float* H1  = smf + EH_F_H1;
    float* W2s = smf + EH_F_W2;
    float* W1c = smf + EH_F_W1C;
    float* b1s = smf + EH_F_B1;
    float* b2s = smf + EH_F_B2;
    float* W3s = smf + EH_F_W3;

    int tid = threadIdx.x, lane = tid & 31, wid = tid >> 5;
    float* eaS = smf + EH_F_EAS + wid*128;
    int*   idS = (int*)(smf + EH_F_IDS) + wid*48;   // eid[16] | src[16] | dst[16]

    if(tid < 128) b1s[tid] = b1[tid];
    else if(tid < 192) b2s[tid-128] = b2[tid-128];
    else               W3s[tid-192] = W3[tid-192];
    {
        int idx = tid*4;
        *reinterpret_cast<float4*>(&W1c[idx]) =
            *reinterpret_cast<const float4*>(&g_W1c[idx]);
    }
    {
        uint32_t* W2u = (uint32_t*)W2s;
        #pragma unroll
        for(int r = 0; r < 8; r++){
            int idx = r*1024 + tid*4;
            int k = idx >> 6, n = idx & 63;
            uint4 v = *reinterpret_cast<const uint4*>(&g_W2u[idx]);
            *(uint4*)(W2u + k*EH_W2_STRIDE + n) = v;
        }
    }
    __syncthreads();

    float bias3 = b3[0];
    uint32_t* H1w = (uint32_t*)(H1 + wid*16*EH_H1_STRIDE);
    int g = lane >> 2, t = lane & 3;
    const uint32_t* W2u = (const uint32_t*)W2s;
    const uint32_t* b_sm = W2u + t*EH_W2_STRIDE + g;

    for(int grp = 0; grp < EG; grp++){
        int e0 = blockIdx.x*EPB + grp*128 + wid*16;   // CSR position base
        if(e0 >= N_EDGES) break;

        // ---- stage per-warp row metadata + ea ----
        if(lane < 16){
            int p = e0 + lane;
            int eid = __ldg(g_csrE + p);
            idS[lane]      = eid;
            idS[16 + lane] = __ldg(g_csr  + p);
            idS[32 + lane] = __ldg(g_csrD + p);
            float4 ev0 = *reinterpret_cast<const float4*>(ea + eid*8);
            float4 ev1 = *reinterpret_cast<const float4*>(ea + eid*8 + 4);
            *(float4*)(eaS + lane*8)     = ev0;
            *(float4*)(eaS + lane*8 + 4) = ev1;
        }
        __syncwarp();

        // ---- phase 1: 4 rows x 16 cols per thread ----
        {
            int rg = lane >> 3, cg = lane & 7;
            int n0 = cg*16;
            float e8r[4][8];
            int src4[4], dst4[4];
            #pragma unroll
            for(int r4 = 0; r4 < 4; r4++){
                int row = rg*4 + r4;
                float4 u0 = *(float4*)(eaS + row*8);
                float4 u1 = *(float4*)(eaS + row*8 + 4);
                e8r[r4][0]=u0.x; e8r[r4][1]=u0.y; e8r[r4][2]=u0.z; e8r[r4][3]=u0.w;
                e8r[r4][4]=u1.x; e8r[r4][5]=u1.y; e8r[r4][6]=u1.z; e8r[r4][7]=u1.w;
                src4[r4] = idS[16 + row];
                dst4[r4] = idS[32 + row];
            }
            #pragma unroll
            for(int jj = 0; jj < 4; jj++){
                int ch = ((cg >> 1) + jj) & 3;
                int c0 = n0 + ch*4;
                float4 w[8];
                #pragma unroll
                for(int k = 0; k < 8; k++)
                    w[k] = *reinterpret_cast<const float4*>(&W1c[k*HID + c0]);
                float4 bb = *reinterpret_cast<const float4*>(&b1s[c0]);
                #pragma unroll
                for(int r4 = 0; r4 < 4; r4++){
                    int row = rg*4 + r4;
                    float4 a = *reinterpret_cast<const float4*>(g_An + src4[r4]*HID + c0);
                    float4 b = *reinterpret_cast<const float4*>(g_Bn + dst4[r4]*HID + c0);
                    float vx = a.x + b.x + bb.x;
                    float vy = a.y + b.y + bb.y;
                    float vz = a.z + b.z + bb.z;
                    float vw = a.w + b.w + bb.w;
                    #pragma unroll
                    for(int k = 0; k < 8; k++){
                        vx += e8r[r4][k]*w[k].x; vy += e8r[r4][k]*w[k].y;
                        vz += e8r[r4][k]*w[k].z; vw += e8r[r4][k]*w[k].w;
                    }
                    uint4 o;
                    o.x = f2tf(fmaxf(vx,0.f)); o.y = f2tf(fmaxf(vy,0.f));
                    o.z = f2tf(fmaxf(vz,0.f)); o.w = f2tf(fmaxf(vw,0.f));
                    *(uint4*)(H1w + row*EH_H1_STRIDE + c0) = o;
                }
            }
        }
        __syncwarp();

        // ---- phase 2: [16 x 64] = H1 @ W2t ; relu(+b2).W3 + b3 ----
        float c2[8][4];
        #pragma unroll
        for(int nf = 0; nf < 8; nf++)
            #pragma unroll
            for(int j = 0; j < 4; j++) c2[nf][j] = 0.f;

        const uint32_t* a_sm = H1w + g*EH_H1_STRIDE + t;
        #pragma unroll
        for(int kk = 0; kk < 16; kk++){
            int k0 = kk*8;
            uint32_t a[4];
            const uint32_t* p = a_sm + k0;
            a[0] = p[0]; a[1] = p[8*EH_H1_STRIDE]; a[2] = p[4]; a[3] = p[8*EH_H1_STRIDE+4];
            const uint32_t* q = b_sm + k0*EH_W2_STRIDE;
            #pragma unroll
            for(int nf = 0; nf < 8; nf++){
                uint32_t b0 = q[nf*8];
                uint32_t b1v = q[4*EH_W2_STRIDE + nf*8];
                mma_tf32(c2[nf], a, b0, b1v);
            }
        }

        #pragma unroll
        for(int rr = 0; rr < 2; rr++){
            float p = 0.f;
            #pragma unroll
            for(int nf = 0; nf < 8; nf++)
                #pragma unroll
                for(int j = 0; j < 2; j++){
                    int col = nf*8 + 2*t + j;
                    p += fmaxf(c2[nf][rr*2+j] + b2s[col], 0.f) * W3s[col];
                }
            p += __shfl_xor_sync(0xffffffffu, p, 1);
            p += __shfl_xor_sync(0xffffffffu, p, 2);
            if(t == 0) out[idS[rr*8 + g]] = p + bias3;
        }
        __syncwarp();
    }
}

// ---------------- launch ----------------
extern "C" void kernel_launch(void* const* d_in, const int* in_sizes, int n_in,
                              void* d_out, int out_size){
    const float* x   = (const float*)d_in[0];
    const int*   ei  = (const int*)  d_in[1];
    const float* ea  = (const float*)d_in[2];
    const float* Win = (const float*)d_in[3];
    const float* bin = (const float*)d_in[4];
    const float* Wl  = (const float*)d_in[5];
    const float* bl  = (const float*)d_in[6];
    const float* Wr  = (const float*)d_in[7];
    const float* lng = (const float*)d_in[8];
    const float* lnb = (const float*)d_in[9];
    const float* W1  = (const float*)d_in[10];
    const float* b1  = (const float*)d_in[11];
    const float* W2  = (const float*)d_in[12];
    const float* b2  = (const float*)d_in[13];
    const float* W3  = (const float*)d_in[14];
    const float* b3  = (const float*)d_in[15];
    const int* src = ei;
    const int* dst = ei + N_EDGES;

    static bool attr_done = false;
    if(!attr_done){
        cudaFuncSetAttribute(gemm_layer<0>, cudaFuncAttributeMaxDynamicSharedMemorySize, GL_SMEM0);
        cudaFuncSetAttribute(gemm_layer<1>, cudaFuncAttributeMaxDynamicSharedMemorySize, GL_SMEM1);
        cudaFuncSetAttribute(edge_k, cudaFuncAttributeMaxDynamicSharedMemorySize, EH_SMEM_BYTES);
        attr_done = true;
    }

    // launches: 0 prep_hist_inproj, 1 scan, 2 fill, 3 agg(l0, also re-zeros cntfill),
    //           4 gemm_layer<0>(l0)  <-- ncu capture slot
    prep_hist_inproj_k<<<PB + EB + NB, 256>>>(dst, x, Win, bin, W1, W2, Wl, Wr);
    scan_k<<<1, 1024>>>();
    fill_k<<<(N_EDGES+255)/256, 256>>>(src, dst);

    const int gb = (N_NODES + 127)/128;  // 391
    uint32_t* Wt0; cudaGetSymbolAddress((void**)&Wt0, g_Wt);
    for(int l = 0; l < 4; l++){
        agg_k<<<(N_NODES+7)/8, 256>>>();
        if(l < 3)
            gemm_layer<0><<<gb, 256, GL_SMEM0>>>(Wt0 + l*HID*256,
                                                 bl + l*HID, lng + l*HID, lnb + l*HID);
        else
            gemm_layer<1><<<gb, 256, GL_SMEM1>>>(Wt0 + l*HID*256,
                                                 bl + l*HID, lng + l*HID, lnb + l*HID);
    }

    edge_k<<<(N_EDGES + EPB - 1)/EPB, 256, EH_SMEM_BYTES>>>(ea, b1, b2, W3, b3, (float*)d_out);
}

// round 13
// speedup vs baseline: 1.0325x; 1.0325x over previous
#include <cuda_runtime.h>
#include <cstdint>

#define N_NODES 50000
#define N_EDGES 800000
#define HID 128

// ---------------- scratch ----------------
__device__ float    g_h  [N_NODES*HID];
__device__ float    g_agg[N_NODES*HID];
__device__ float    g_An [N_NODES*HID];
__device__ float    g_Bn [N_NODES*HID];
__device__ int      g_cntfill[2*N_NODES];      // [cnt | fill]
__device__ int      g_rowptr[N_NODES+1];
__device__ int      g_csr [N_EDGES];           // src per CSR position
__device__ int      g_csrE[N_EDGES];           // original edge id per CSR position
__device__ int      g_csrD[N_EDGES];           // dst per CSR position
__device__ uint32_t g_Wt [4*HID*256];          // tf32 [l][n][k] combined Wl|Wr
__device__ uint32_t g_W1s[2*HID*HID];          // tf32 [slice][n][k] from W1
__device__ uint32_t g_W2u[HID*64];             // tf32 [k][c] W2 transposed
__device__ float    g_W1c[8*HID];              // fp32 W1 cols 256..263 transposed

// ---------------- tf32 mma helpers ----------------
__device__ __forceinline__ uint32_t f2tf(float f){
    uint32_t r;
    asm("cvt.rna.tf32.f32 %0, %1;" : "=r"(r) : "f"(f));
    return r;
}
__device__ __forceinline__ void mma_tf32(float* c, const uint32_t* a, uint32_t b0, uint32_t b1){
    asm volatile("mma.sync.aligned.m16n8k8.row.col.f32.tf32.tf32.f32 "
        "{%0,%1,%2,%3}, {%4,%5,%6,%7}, {%8,%9}, {%0,%1,%2,%3};"
        : "+f"(c[0]), "+f"(c[1]), "+f"(c[2]), "+f"(c[3])
        : "r"(a[0]), "r"(a[1]), "r"(a[2]), "r"(a[3]), "r"(b0), "r"(b1));
}

// ---------------- combo: weight prep + hist + input projection ----------------
#define PB 512                           // prep blocks (4*128*256/256)
#define EB ((N_EDGES+255)/256)           // 3125
#define NB ((N_NODES+1)/2)               // 25000

__global__ void prep_hist_inproj_k(const int* __restrict__ dst, const float* __restrict__ x,
                                   const float* __restrict__ Win, const float* __restrict__ bin,
                                   const float* __restrict__ W1, const float* __restrict__ W2,
                                   const float* __restrict__ Wl, const float* __restrict__ Wr){
    if(blockIdx.x < PB){
        int i = blockIdx.x*256 + threadIdx.x;
        if(i < 4*HID*256){
            int l = i >> 15; int r = i & 32767; int n = r >> 8, k = r & 255;
            float v = (k < 128) ? Wl[l*16384 + n*128 + k] : Wr[l*16384 + n*128 + (k-128)];
            g_Wt[i] = f2tf(v);
        }
        if(i < 2*HID*HID){
            int s = i >> 14; int r = i & 16383; int n = r >> 7, k = r & 127;
            g_W1s[i] = f2tf(W1[n*264 + s*128 + k]);
        }
        if(i < HID*64){ int k = i/64, c = i%64; g_W2u[i] = f2tf(W2[c*HID + k]); }
        if(i < 8*HID) { int k = i/HID, c = i%HID; g_W1c[i] = W1[c*264 + 256 + k]; }
        return;
    }
    if(blockIdx.x < PB + EB){
        int i = (blockIdx.x - PB)*256 + threadIdx.x;
        if(i < N_EDGES) atomicAdd(&g_cntfill[dst[i]], 1);
        return;
    }
    __shared__ float xs[2][16];
    int tid = threadIdx.x;
    int n0 = (blockIdx.x - PB - EB)*2;
    if(tid < 32){
        int nn = tid/16, k = tid%16;
        int n = n0 + nn;
        xs[nn][k] = (n < N_NODES) ? x[n*16 + k] : 0.f;
    }
    __syncthreads();
    int nn = tid/HID, c = tid%HID;
    int n = n0 + nn;
    if(n < N_NODES){
        float acc = bin[c];
        const float* w = Win + c*16;
        #pragma unroll
        for(int k = 0; k < 16; k++) acc += xs[nn][k]*w[k];
        g_h[n*HID + c] = acc;
    }
}

// ---------------- fast scan ----------------
#define SCH 49   // ceil(50000/1024)

__global__ void scan_k(){
    __shared__ int ssum[1024];
    int tid = threadIdx.x;
    int base = tid*SCH;
    int v[SCH];
    int tot = 0;
    #pragma unroll
    for(int j = 0; j < SCH; j++){
        int i = base + j;
        v[j] = (i < N_NODES) ? g_cntfill[i] : 0;
        tot += v[j];
    }
    ssum[tid] = tot;
    __syncthreads();
    for(int off = 1; off < 1024; off <<= 1){
        int t = (tid >= off) ? ssum[tid-off] : 0;
        __syncthreads();
        ssum[tid] += t;
        __syncthreads();
    }
    int run = ssum[tid] - tot;
    #pragma unroll
    for(int j = 0; j < SCH; j++){
        int i = base + j;
        if(i < N_NODES) g_rowptr[i] = run;
        run += v[j];
    }
    if(tid == 1023) g_rowptr[N_NODES] = run;
}

__global__ void fill_k(const int* __restrict__ src, const int* __restrict__ dst){
    int i = blockIdx.x*blockDim.x + threadIdx.x;
    if(i < N_EDGES){
        int d = dst[i];
        int pos = g_rowptr[d] + atomicAdd(&g_cntfill[N_NODES + d], 1);
        g_csr [pos] = src[i];
        g_csrE[pos] = i;
        g_csrD[pos] = d;
    }
}

// ---------------- mean aggregation (CSR gather, MLP=4) + cntfill re-zero ----------------
__global__ void agg_k(){
    // reset histogram/fill counters for the NEXT graph replay (runs after fill_k)
    int z = blockIdx.x*blockDim.x + threadIdx.x;
    if(z < 2*N_NODES) g_cntfill[z] = 0;

    int warp = threadIdx.x >> 5, lane = threadIdx.x & 31;
    int n = blockIdx.x*8 + warp;
    if(n >= N_NODES) return;
    int beg = g_rowptr[n], end = g_rowptr[n+1];
    float4 acc = make_float4(0.f,0.f,0.f,0.f);
    const float4* hp = reinterpret_cast<const float4*>(g_h);
    int j = beg;
    for(; j + 4 <= end; j += 4){
        int s0 = g_csr[j], s1 = g_csr[j+1], s2 = g_csr[j+2], s3 = g_csr[j+3];
        float4 v0 = hp[s0*32 + lane];
        float4 v1 = hp[s1*32 + lane];
        float4 v2 = hp[s2*32 + lane];
        float4 v3 = hp[s3*32 + lane];
        acc.x += (v0.x+v1.x) + (v2.x+v3.x);
        acc.y += (v0.y+v1.y) + (v2.y+v3.y);
        acc.z += (v0.z+v1.z) + (v2.z+v3.z);
        acc.w += (v0.w+v1.w) + (v2.w+v3.w);
    }
    for(; j < end; j++){
        int s = g_csr[j];
        float4 v = hp[s*32 + lane];
        acc.x += v.x; acc.y += v.y; acc.z += v.z; acc.w += v.w;
    }
    float inv = (end > beg) ? 1.0f/(float)(end - beg) : 0.0f;
    acc.x *= inv; acc.y *= inv; acc.z *= inv; acc.w *= inv;
    reinterpret_cast<float4*>(g_agg)[n*32 + lane] = acc;
}

// ---------------- layer GEMM (K=256, single-buffer R11) + bias/LN/ReLU; FUSE=1 emits An/Bn ----------------
#define GL_AS   0
#define GL_BS   (128*36)
#define GL_PRM  (GL_BS + 128*36)
#define GL_PS   (GL_PRM + 384)
#define GL_PQ   (GL_PS + 256)
#define GL_HS   (GL_PQ + 256)
#define GL_SMEM0 (GL_HS*4)
#define GL_SMEM1 ((GL_HS + 128*132)*4)

template<int FUSE>
__global__ void __launch_bounds__(256) gemm_layer(
        const uint32_t* __restrict__ Wt,
        const float* __restrict__ bias, const float* __restrict__ lng,
        const float* __restrict__ lnb){
    extern __shared__ uint32_t smu[];
    uint32_t* As = smu + GL_AS;
    uint32_t* Bs = smu + GL_BS;
    float* prm = (float*)(smu + GL_PRM);
    float* ps  = (float*)(smu + GL_PS);
    float* pq  = (float*)(smu + GL_PQ);
    uint32_t* Hs = smu + GL_HS;

    int tid = threadIdx.x;
    int lane = tid & 31, wid = tid >> 5;
    int g = lane >> 2, t = lane & 3;
    int wy = wid & 3, wx = wid >> 2;
    int m0 = blockIdx.x*128;

    float c[2][8][4];
    #pragma unroll
    for(int mi = 0; mi < 2; mi++)
        #pragma unroll
        for(int nf = 0; nf < 8; nf++)
            #pragma unroll
            for(int j = 0; j < 4; j++) c[mi][nf][j] = 0.f;

    if(tid < 128){
        prm[tid] = bias[tid]; prm[128+tid] = lng[tid]; prm[256+tid] = lnb[tid];
    }

    float4 sa[4]; uint4 sb[4];
    {
        #pragma unroll
        for(int i = 0; i < 4; i++){
            int s = tid + i*256;
            int r = s >> 3, c4 = (s & 7)*4;
            int mr = m0 + r; if(mr >= N_NODES) mr = N_NODES-1;
            sa[i] = *(const float4*)(g_agg + mr*128 + c4);
            sb[i] = *(const uint4*)(Wt + r*256 + c4);
        }
    }

    for(int ch = 0; ch < 8; ch++){
        #pragma unroll
        for(int i = 0; i < 4; i++){
            int s = tid + i*256;
            int r = s >> 3, c4 = (s & 7)*4;
            uint32_t* d = As + r*36 + c4;
            d[0] = f2tf(sa[i].x); d[1] = f2tf(sa[i].y); d[2] = f2tf(sa[i].z); d[3] = f2tf(sa[i].w);
            *(uint4*)(Bs + r*36 + c4) = sb[i];
        }
        __syncthreads();
        if(ch + 1 < 8){
            int nc = ch + 1;
            const float* Ap = (nc < 4) ? g_agg : g_h;
            int kc = (nc & 3)*32;
            #pragma unroll
            for(int i = 0; i < 4; i++){
                int s = tid + i*256;
                int r = s >> 3, c4 = (s & 7)*4;
                int mr = m0 + r; if(mr >= N_NODES) mr = N_NODES-1;
                sa[i] = *(const float4*)(Ap + mr*128 + kc + c4);
                sb[i] = *(const uint4*)(Wt + r*256 + nc*32 + c4);
            }
        }
        const uint32_t* a_sm = As + (wy*32 + g)*36 + t;
        const uint32_t* b_sm = Bs + (wx*64 + g)*36 + t;
        #pragma unroll
        for(int kk = 0; kk < 4; kk++){
            int k0 = kk*8;
            uint32_t a[2][4];
            #pragma unroll
            for(int mi = 0; mi < 2; mi++){
                const uint32_t* p = a_sm + mi*16*36 + k0;
                a[mi][0] = p[0]; a[mi][1] = p[8*36]; a[mi][2] = p[4]; a[mi][3] = p[8*36+4];
            }
            #pragma unroll
            for(int nf = 0; nf < 8; nf++){
                const uint32_t* q = b_sm + nf*8*36 + k0;
                uint32_t b0 = q[0], b1 = q[4];
                mma_tf32(c[0][nf], a[0], b0, b1);
                mma_tf32(c[1][nf], a[1], b0, b1);
            }
        }
        __syncthreads();
    }

    int colb = wx*64;
    #pragma unroll
    for(int mi = 0; mi < 2; mi++)
        #pragma unroll
        for(int rr = 0; rr < 2; rr++){
            float s = 0.f, sq = 0.f;
            #pragma unroll
            for(int nf = 0; nf < 8; nf++)
                #pragma unroll
                for(int j = 0; j < 2; j++){
                    int col = colb + nf*8 + 2*t + j;
                    float v = c[mi][nf][rr*2+j] + prm[col];
                    c[mi][nf][rr*2+j] = v;
                    s += v; sq += v*v;
                }
            s  += __shfl_xor_sync(0xffffffffu, s, 1);
            s  += __shfl_xor_sync(0xffffffffu, s, 2);
            sq += __shfl_xor_sync(0xffffffffu, sq, 1);
            sq += __shfl_xor_sync(0xffffffffu, sq, 2);
            if(t == 0){
                int row = wy*32 + mi*16 + rr*8 + g;
                ps[wx*128 + row] = s;
                pq[wx*128 + row] = sq;
            }
        }
    __syncthreads();
    #pragma unroll
    for(int mi = 0; mi < 2; mi++)
        #pragma unroll
        for(int rr = 0; rr < 2; rr++){
            int row = wy*32 + mi*16 + rr*8 + g;
            int m = m0 + row;
            float st  = ps[row] + ps[128+row];
            float sqt = pq[row] + pq[128+row];
            float mu  = st * (1.0f/128.0f);
            float var = sqt * (1.0f/128.0f) - mu*mu;
            float rs  = rsqrtf(var + 1e-5f);
            #pragma unroll
            for(int nf = 0; nf < 8; nf++){
                int col = colb + nf*8 + 2*t;
                float2 o;
                o.x = fmaxf((c[mi][nf][rr*2+0]-mu)*rs*prm[128+col]   + prm[256+col],   0.f);
                o.y = fmaxf((c[mi][nf][rr*2+1]-mu)*rs*prm[128+col+1] + prm[256+col+1], 0.f);
                if(m < N_NODES) *(float2*)(g_h + m*128 + col) = o;
                if(FUSE){
                    Hs[row*132 + col]   = f2tf(o.x);
                    Hs[row*132 + col+1] = f2tf(o.y);
                }
            }
        }

    if(FUSE){
        __syncthreads();
        #pragma unroll
        for(int sl = 0; sl < 2; sl++){
            const uint32_t* W = g_W1s + sl*16384;
            #pragma unroll
            for(int mi = 0; mi < 2; mi++)
                #pragma unroll
                for(int nf = 0; nf < 8; nf++)
                    #pragma unroll
                    for(int j = 0; j < 4; j++) c[mi][nf][j] = 0.f;

            uint4 sb2[4];
            #pragma unroll
            for(int i = 0; i < 4; i++){
                int s = tid + i*256;
                int r = s >> 3, c4 = (s & 7)*4;
                sb2[i] = *(const uint4*)(W + r*128 + c4);
            }
            for(int ch = 0; ch < 4; ch++){
                #pragma unroll
                for(int i = 0; i < 4; i++){
                    int s = tid + i*256;
                    int r = s >> 3, c4 = (s & 7)*4;
                    *(uint4*)(Bs + r*36 + c4) = sb2[i];
                }
                __syncthreads();
                if(ch + 1 < 4){
                    int nc = ch + 1;
                    #pragma unroll
                    for(int i = 0; i < 4; i++){
                        int s = tid + i*256;
                        int r = s >> 3, c4 = (s & 7)*4;
                        sb2[i] = *(const uint4*)(W + r*128 + nc*32 + c4);
                    }
                }
                const uint32_t* a_sm = Hs + (wy*32 + g)*132 + ch*32 + t;
                const uint32_t* b_sm = Bs + (wx*64 + g)*36 + t;
                #pragma unroll
                for(int kk = 0; kk < 4; kk++){
                    int k0 = kk*8;
                    uint32_t a[2][4];
                    #pragma unroll
                    for(int mi = 0; mi < 2; mi++){
                        const uint32_t* p = a_sm + mi*16*132 + k0;
                        a[mi][0] = p[0]; a[mi][1] = p[8*132]; a[mi][2] = p[4]; a[mi][3] = p[8*132+4];
                    }
                    #pragma unroll
                    for(int nf = 0; nf < 8; nf++){
                        const uint32_t* q = b_sm + nf*8*36 + k0;
                        uint32_t b0 = q[0], b1 = q[4];
                        mma_tf32(c[0][nf], a[0], b0, b1);
                        mma_tf32(c[1][nf], a[1], b0, b1);
                    }
                }
                __syncthreads();
            }
            float* out = sl ? g_Bn : g_An;
            #pragma unroll
            for(int mi = 0; mi < 2; mi++)
                #pragma unroll
                for(int rr = 0; rr < 2; rr++){
                    int row = wy*32 + mi*16 + rr*8 + g;
                    int m = m0 + row;
                    if(m < N_NODES){
                        #pragma unroll
                        for(int nf = 0; nf < 8; nf++){
                            int col = colb + nf*8 + 2*t;
                            *(float2*)(out + m*128 + col) =
                                make_float2(c[mi][nf][rr*2+0], c[mi][nf][rr*2+1]);
                        }
                    }
                }
        }
    }
}

// ---------------- edge head: CSR-order, warp-pipelined, 4x16 register-blocked phase 1 ----------------
#define EG 8
#define EPB (128*EG)
#define EH_H1_STRIDE 132
#define EH_W2_STRIDE 72
#define EH_F_H1   0
#define EH_F_W2   (EH_F_H1 + 128*EH_H1_STRIDE)
#define EH_F_W1C  (EH_F_W2 + 128*EH_W2_STRIDE)
#define EH_F_B1   (EH_F_W1C + 8*128)
#define EH_F_B2   (EH_F_B1 + 128)
#define EH_F_W3   (EH_F_B2 + 64)
#define EH_F_EAS  (EH_F_W3 + 64)          // [8 warps][128] floats
#define EH_F_IDS  (EH_F_EAS + 8*128)      // [8 warps][48] ints (eid|src|dst x16)
#define EH_F_END  (EH_F_IDS + 8*48)
#define EH_SMEM_BYTES (EH_F_END*4 + 64)

__global__ void __launch_bounds__(256) edge_k(
        const float* __restrict__ ea,
        const float* __restrict__ b1, const float* __restrict__ b2,
        const float* __restrict__ W3, const float* __restrict__ b3,
        float* __restrict__ out){
    extern __shared__ float smf[];
    float* H1  = smf + EH_F_H1;
    float* W2s = smf + EH_F_W2;
    float* W1c = smf + EH_F_W1C;
    float* b1s = smf + EH_F_B1;
    float* b2s = smf + EH_F_B2;
    float* W3s = smf + EH_F_W3;

    int tid = threadIdx.x, lane = tid & 31, wid = tid >> 5;
    float* eaS = smf + EH_F_EAS + wid*128;
    int*   idS = (int*)(smf + EH_F_IDS) + wid*48;   // eid[16] | src[16] | dst[16]

    if(tid < 128) b1s[tid] = b1[tid];
    else if(tid < 192) b2s[tid-128] = b2[tid-128];
    else               W3s[tid-192] = W3[tid-192];
    {
        int idx = tid*4;
        *reinterpret_cast<float4*>(&W1c[idx]) =
            *reinterpret_cast<const float4*>(&g_W1c[idx]);
    }
    {
        uint32_t* W2u = (uint32_t*)W2s;
        #pragma unroll
        for(int r = 0; r < 8; r++){
            int idx = r*1024 + tid*4;
            int k = idx >> 6, n = idx & 63;
            uint4 v = *reinterpret_cast<const uint4*>(&g_W2u[idx]);
            *(uint4*)(W2u + k*EH_W2_STRIDE + n) = v;
        }
    }
    __syncthreads();

    float bias3 = b3[0];
    uint32_t* H1w = (uint32_t*)(H1 + wid*16*EH_H1_STRIDE);
    int g = lane >> 2, t = lane & 3;
    const uint32_t* W2u = (const uint32_t*)W2s;
    const uint32_t* b_sm = W2u + t*EH_W2_STRIDE + g;

    for(int grp = 0; grp < EG; grp++){
        int e0 = blockIdx.x*EPB + grp*128 + wid*16;   // CSR position base
        if(e0 >= N_EDGES) break;

        // ---- stage per-warp row metadata + ea ----
        if(lane < 16){
            int p = e0 + lane;
            int eid = __ldg(g_csrE + p);
            idS[lane]      = eid;
            idS[16 + lane] = __ldg(g_csr  + p);
            idS[32 + lane] = __ldg(g_csrD + p);
            float4 ev0 = *reinterpret_cast<const float4*>(ea + eid*8);
            float4 ev1 = *reinterpret_cast<const float4*>(ea + eid*8 + 4);
            *(float4*)(eaS + lane*8)     = ev0;
            *(float4*)(eaS + lane*8 + 4) = ev1;
        }
        __syncwarp();

        // ---- phase 1: 4 rows x 16 cols per thread ----
        {
            int rg = lane >> 3, cg = lane & 7;
            int n0 = cg*16;
            float e8r[4][8];
            int src4[4], dst4[4];
            #pragma unroll
            for(int r4 = 0; r4 < 4; r4++){
                int row = rg*4 + r4;
                float4 u0 = *(float4*)(eaS + row*8);
                float4 u1 = *(float4*)(eaS + row*8 + 4);
                e8r[r4][0]=u0.x; e8r[r4][1]=u0.y; e8r[r4][2]=u0.z; e8r[r4][3]=u0.w;
                e8r[r4][4]=u1.x; e8r[r4][5]=u1.y; e8r[r4][6]=u1.z; e8r[r4][7]=u1.w;
                src4[r4] = idS[16 + row];
                dst4[r4] = idS[32 + row];
            }
            #pragma unroll
            for(int jj = 0; jj < 4; jj++){
                int ch = ((cg >> 1) + jj) & 3;
                int c0 = n0 + ch*4;
                float4 w[8];
                #pragma unroll
                for(int k = 0; k < 8; k++)
                    w[k] = *reinterpret_cast<const float4*>(&W1c[k*HID + c0]);
                float4 bb = *reinterpret_cast<const float4*>(&b1s[c0]);
                #pragma unroll
                for(int r4 = 0; r4 < 4; r4++){
                    int row = rg*4 + r4;
                    float4 a = *reinterpret_cast<const float4*>(g_An + src4[r4]*HID + c0);
                    float4 b = *reinterpret_cast<const float4*>(g_Bn + dst4[r4]*HID + c0);
                    float vx = a.x + b.x + bb.x;
                    float vy = a.y + b.y + bb.y;
                    float vz = a.z + b.z + bb.z;
                    float vw = a.w + b.w + bb.w;
                    #pragma unroll
                    for(int k = 0; k < 8; k++){
                        vx += e8r[r4][k]*w[k].x; vy += e8r[r4][k]*w[k].y;
                        vz += e8r[r4][k]*w[k].z; vw += e8r[r4][k]*w[k].w;
                    }
                    uint4 o;
                    o.x = f2tf(fmaxf(vx,0.f)); o.y = f2tf(fmaxf(vy,0.f));
                    o.z = f2tf(fmaxf(vz,0.f)); o.w = f2tf(fmaxf(vw,0.f));
                    *(uint4*)(H1w + row*EH_H1_STRIDE + c0) = o;
                }
            }
        }
        __syncwarp();

        // ---- phase 2: [16 x 64] = H1 @ W2t ; relu(+b2).W3 + b3 ----
        float c2[8][4];
        #pragma unroll
        for(int nf = 0; nf < 8; nf++)
            #pragma unroll
            for(int j = 0; j < 4; j++) c2[nf][j] = 0.f;

        const uint32_t* a_sm = H1w + g*EH_H1_STRIDE + t;
        #pragma unroll
        for(int kk = 0; kk < 16; kk++){
            int k0 = kk*8;
            uint32_t a[4];
            const uint32_t* p = a_sm + k0;
            a[0] = p[0]; a[1] = p[8*EH_H1_STRIDE]; a[2] = p[4]; a[3] = p[8*EH_H1_STRIDE+4];
            const uint32_t* q = b_sm + k0*EH_W2_STRIDE;
            #pragma unroll
            for(int nf = 0; nf < 8; nf++){
                uint32_t b0 = q[nf*8];
                uint32_t b1v = q[4*EH_W2_STRIDE + nf*8];
                mma_tf32(c2[nf], a, b0, b1v);
            }
        }

        #pragma unroll
        for(int rr = 0; rr < 2; rr++){
            float p = 0.f;
            #pragma unroll
            for(int nf = 0; nf < 8; nf++)
                #pragma unroll
                for(int j = 0; j < 2; j++){
                    int col = nf*8 + 2*t + j;
                    p += fmaxf(c2[nf][rr*2+j] + b2s[col], 0.f) * W3s[col];
                }
            p += __shfl_xor_sync(0xffffffffu, p, 1);
            p += __shfl_xor_sync(0xffffffffu, p, 2);
            if(t == 0) out[idS[rr*8 + g]] = p + bias3;
        }
        __syncwarp();
    }
}

// ---------------- launch ----------------
extern "C" void kernel_launch(void* const* d_in, const int* in_sizes, int n_in,
                              void* d_out, int out_size){
    const float* x   = (const float*)d_in[0];
    const int*   ei  = (const int*)  d_in[1];
    const float* ea  = (const float*)d_in[2];
    const float* Win = (const float*)d_in[3];
    const float* bin = (const float*)d_in[4];
    const float* Wl  = (const float*)d_in[5];
    const float* bl  = (const float*)d_in[6];
    const float* Wr  = (const float*)d_in[7];
    const float* lng = (const float*)d_in[8];
    const float* lnb = (const float*)d_in[9];
    const float* W1  = (const float*)d_in[10];
    const float* b1  = (const float*)d_in[11];
    const float* W2  = (const float*)d_in[12];
    const float* b2  = (const float*)d_in[13];
    const float* W3  = (const float*)d_in[14];
    const float* b3  = (const float*)d_in[15];
    const int* src = ei;
    const int* dst = ei + N_EDGES;

    static bool attr_done = false;
    if(!attr_done){
        cudaFuncSetAttribute(gemm_layer<1>, cudaFuncAttributeMaxDynamicSharedMemorySize, GL_SMEM1);
        cudaFuncSetAttribute(edge_k, cudaFuncAttributeMaxDynamicSharedMemorySize, EH_SMEM_BYTES);
        attr_done = true;
    }

    prep_hist_inproj_k<<<PB + EB + NB, 256>>>(dst, x, Win, bin, W1, W2, Wl, Wr);
    scan_k<<<1, 1024>>>();
    fill_k<<<(N_EDGES+255)/256, 256>>>(src, dst);

    const int gb = (N_NODES + 127)/128;  // 391
    uint32_t* Wt0; cudaGetSymbolAddress((void**)&Wt0, g_Wt);
    for(int l = 0; l < 4; l++){
        agg_k<<<(N_NODES+7)/8, 256>>>();
        if(l < 3)
            gemm_layer<0><<<gb, 256, GL_SMEM0>>>(Wt0 + l*HID*256,
                                                 bl + l*HID, lng + l*HID, lnb + l*HID);
        else
            gemm_layer<1><<<gb, 256, GL_SMEM1>>>(Wt0 + l*HID*256,
                                                 bl + l*HID, lng + l*HID, lnb + l*HID);
    }

    edge_k<<<(N_EDGES + EPB - 1)/EPB, 256, EH_SMEM_BYTES>>>(ea, b1, b2, W3, b3, (float*)d_out);
}

// round 14
// speedup vs baseline: 1.0443x; 1.0114x over previous
#include <cuda_runtime.h>
#include <cstdint>

#define N_NODES 50000
#define N_EDGES 800000
#define HID 128

// ---------------- scratch ----------------
__device__ float    g_h  [N_NODES*HID];
__device__ float    g_agg[N_NODES*HID];
__device__ float    g_An [N_NODES*HID];
__device__ float    g_Bn [N_NODES*HID];
__device__ int      g_cntfill[2*N_NODES];      // [cnt | fill]
__device__ int      g_rowptr[N_NODES+1];
__device__ int      g_csr [N_EDGES];           // src per CSR position
__device__ int      g_csrE[N_EDGES];           // original edge id per CSR position
__device__ int      g_csrD[N_EDGES];           // dst per CSR position
__device__ uint32_t g_Wt [4*HID*256];          // tf32 [l][n][k] combined Wl|Wr
__device__ uint32_t g_W1s[2*HID*HID];          // tf32 [slice][n][k] from W1
__device__ uint32_t g_W2u[HID*64];             // tf32 [k][c] W2 transposed
__device__ float    g_W1c[8*HID];              // fp32 W1 cols 256..263 transposed

// ---------------- tf32 mma helpers ----------------
__device__ __forceinline__ uint32_t f2tf(float f){
    uint32_t r;
    asm("cvt.rna.tf32.f32 %0, %1;" : "=r"(r) : "f"(f));
    return r;
}
__device__ __forceinline__ void mma_tf32(float* c, const uint32_t* a, uint32_t b0, uint32_t b1){
    asm volatile("mma.sync.aligned.m16n8k8.row.col.f32.tf32.tf32.f32 "
        "{%0,%1,%2,%3}, {%4,%5,%6,%7}, {%8,%9}, {%0,%1,%2,%3};"
        : "+f"(c[0]), "+f"(c[1]), "+f"(c[2]), "+f"(c[3])
        : "r"(a[0]), "r"(a[1]), "r"(a[2]), "r"(a[3]), "r"(b0), "r"(b1));
}

// ---------------- combo: weight prep + hist + input projection ----------------
#define PB 512                           // prep blocks (4*128*256/256)
#define EB ((N_EDGES+255)/256)           // 3125
#define NB ((N_NODES+1)/2)               // 25000

__global__ void prep_hist_inproj_k(const int* __restrict__ dst, const float* __restrict__ x,
                                   const float* __restrict__ Win, const float* __restrict__ bin,
                                   const float* __restrict__ W1, const float* __restrict__ W2,
                                   const float* __restrict__ Wl, const float* __restrict__ Wr){
    if(blockIdx.x < PB){
        int i = blockIdx.x*256 + threadIdx.x;
        if(i < 4*HID*256){
            int l = i >> 15; int r = i & 32767; int n = r >> 8, k = r & 255;
            float v = (k < 128) ? Wl[l*16384 + n*128 + k] : Wr[l*16384 + n*128 + (k-128)];
            g_Wt[i] = f2tf(v);
        }
        if(i < 2*HID*HID){
            int s = i >> 14; int r = i & 16383; int n = r >> 7, k = r & 127;
            g_W1s[i] = f2tf(W1[n*264 + s*128 + k]);
        }
        if(i < HID*64){ int k = i/64, c = i%64; g_W2u[i] = f2tf(W2[c*HID + k]); }
        if(i < 8*HID) { int k = i/HID, c = i%HID; g_W1c[i] = W1[c*264 + 256 + k]; }
        return;
    }
    if(blockIdx.x < PB + EB){
        int i = (blockIdx.x - PB)*256 + threadIdx.x;
        if(i < N_EDGES) atomicAdd(&g_cntfill[dst[i]], 1);
        return;
    }
    __shared__ float xs[2][16];
    int tid = threadIdx.x;
    int n0 = (blockIdx.x - PB - EB)*2;
    if(tid < 32){
        int nn = tid/16, k = tid%16;
        int n = n0 + nn;
        xs[nn][k] = (n < N_NODES) ? x[n*16 + k] : 0.f;
    }
    __syncthreads();
    int nn = tid/HID, c = tid%HID;
    int n = n0 + nn;
    if(n < N_NODES){
        float acc = bin[c];
        const float* w = Win + c*16;
        #pragma unroll
        for(int k = 0; k < 16; k++) acc += xs[nn][k]*w[k];
        g_h[n*HID + c] = acc;
    }
}

// ---------------- fast scan ----------------
#define SCH 49   // ceil(50000/1024)

__global__ void scan_k(){
    __shared__ int ssum[1024];
    int tid = threadIdx.x;
    int base = tid*SCH;
    int v[SCH];
    int tot = 0;
    #pragma unroll
    for(int j = 0; j < SCH; j++){
        int i = base + j;
        v[j] = (i < N_NODES) ? g_cntfill[i] : 0;
        tot += v[j];
    }
    ssum[tid] = tot;
    __syncthreads();
    for(int off = 1; off < 1024; off <<= 1){
        int t = (tid >= off) ? ssum[tid-off] : 0;
        __syncthreads();
        ssum[tid] += t;
        __syncthreads();
    }
    int run = ssum[tid] - tot;
    #pragma unroll
    for(int j = 0; j < SCH; j++){
        int i = base + j;
        if(i < N_NODES) g_rowptr[i] = run;
        run += v[j];
    }
    if(tid == 1023) g_rowptr[N_NODES] = run;
}

__global__ void fill_k(const int* __restrict__ src, const int* __restrict__ dst){
    int i = blockIdx.x*blockDim.x + threadIdx.x;
    if(i < N_EDGES){
        int d = dst[i];
        int pos = g_rowptr[d] + atomicAdd(&g_cntfill[N_NODES + d], 1);
        g_csr [pos] = src[i];
        g_csrE[pos] = i;
        g_csrD[pos] = d;
    }
}

// ---------------- mean aggregation (CSR gather, MLP=8) + cntfill re-zero ----------------
__global__ void agg_k(){
    int z = blockIdx.x*blockDim.x + threadIdx.x;
    if(z < 2*N_NODES) g_cntfill[z] = 0;

    int warp = threadIdx.x >> 5, lane = threadIdx.x & 31;
    int n = blockIdx.x*8 + warp;
    if(n >= N_NODES) return;
    int beg = g_rowptr[n], end = g_rowptr[n+1];
    float4 acc0 = make_float4(0.f,0.f,0.f,0.f);
    float4 acc1 = make_float4(0.f,0.f,0.f,0.f);
    const float4* hp = reinterpret_cast<const float4*>(g_h);
    int j = beg;
    for(; j + 8 <= end; j += 8){
        int s0 = g_csr[j],   s1 = g_csr[j+1], s2 = g_csr[j+2], s3 = g_csr[j+3];
        int s4 = g_csr[j+4], s5 = g_csr[j+5], s6 = g_csr[j+6], s7 = g_csr[j+7];
        float4 v0 = hp[s0*32 + lane];
        float4 v1 = hp[s1*32 + lane];
        float4 v2 = hp[s2*32 + lane];
        float4 v3 = hp[s3*32 + lane];
        float4 v4 = hp[s4*32 + lane];
        float4 v5 = hp[s5*32 + lane];
        float4 v6 = hp[s6*32 + lane];
        float4 v7 = hp[s7*32 + lane];
        acc0.x += (v0.x+v1.x) + (v2.x+v3.x);
        acc0.y += (v0.y+v1.y) + (v2.y+v3.y);
        acc0.z += (v0.z+v1.z) + (v2.z+v3.z);
        acc0.w += (v0.w+v1.w) + (v2.w+v3.w);
        acc1.x += (v4.x+v5.x) + (v6.x+v7.x);
        acc1.y += (v4.y+v5.y) + (v6.y+v7.y);
        acc1.z += (v4.z+v5.z) + (v6.z+v7.z);
        acc1.w += (v4.w+v5.w) + (v6.w+v7.w);
    }
    for(; j + 4 <= end; j += 4){
        int s0 = g_csr[j], s1 = g_csr[j+1], s2 = g_csr[j+2], s3 = g_csr[j+3];
        float4 v0 = hp[s0*32 + lane];
        float4 v1 = hp[s1*32 + lane];
        float4 v2 = hp[s2*32 + lane];
        float4 v3 = hp[s3*32 + lane];
        acc0.x += (v0.x+v1.x) + (v2.x+v3.x);
        acc0.y += (v0.y+v1.y) + (v2.y+v3.y);
        acc0.z += (v0.z+v1.z) + (v2.z+v3.z);
        acc0.w += (v0.w+v1.w) + (v2.w+v3.w);
    }
    for(; j < end; j++){
        int s = g_csr[j];
        float4 v = hp[s*32 + lane];
        acc0.x += v.x; acc0.y += v.y; acc0.z += v.z; acc0.w += v.w;
    }
    acc0.x += acc1.x; acc0.y += acc1.y; acc0.z += acc1.z; acc0.w += acc1.w;
    float inv = (end > beg) ? 1.0f/(float)(end - beg) : 0.0f;
    acc0.x *= inv; acc0.y *= inv; acc0.z *= inv; acc0.w *= inv;
    reinterpret_cast<float4*>(g_agg)[n*32 + lane] = acc0;
}

// ---------------- layer GEMM (K=256, single-buffer R11) + bias/LN/ReLU; FUSE=1 emits An/Bn ----------------
#define GL_AS   0
#define GL_BS   (128*36)
#define GL_PRM  (GL_BS + 128*36)
#define GL_PS   (GL_PRM + 384)
#define GL_PQ   (GL_PS + 256)
#define GL_HS   (GL_PQ + 256)
#define GL_SMEM0 (GL_HS*4)
#define GL_SMEM1 ((GL_HS + 128*132)*4)

template<int FUSE>
__global__ void __launch_bounds__(256) gemm_layer(
        const uint32_t* __restrict__ Wt,
        const float* __restrict__ bias, const float* __restrict__ lng,
        const float* __restrict__ lnb){
    extern __shared__ uint32_t smu[];
    uint32_t* As = smu + GL_AS;
    uint32_t* Bs = smu + GL_BS;
    float* prm = (float*)(smu + GL_PRM);
    float* ps  = (float*)(smu + GL_PS);
    float* pq  = (float*)(smu + GL_PQ);
    uint32_t* Hs = smu + GL_HS;

    int tid = threadIdx.x;
    int lane = tid & 31, wid = tid >> 5;
    int g = lane >> 2, t = lane & 3;
    int wy = wid & 3, wx = wid >> 2;
    int m0 = blockIdx.x*128;

    float c[2][8][4];
    #pragma unroll
    for(int mi = 0; mi < 2; mi++)
        #pragma unroll
        for(int nf = 0; nf < 8; nf++)
            #pragma unroll
            for(int j = 0; j < 4; j++) c[mi][nf][j] = 0.f;

    if(tid < 128){
        prm[tid] = bias[tid]; prm[128+tid] = lng[tid]; prm[256+tid] = lnb[tid];
    }

    float4 sa[4]; uint4 sb[4];
    {
        #pragma unroll
        for(int i = 0; i < 4; i++){
            int s = tid + i*256;
            int r = s >> 3, c4 = (s & 7)*4;
            int mr = m0 + r; if(mr >= N_NODES) mr = N_NODES-1;
            sa[i] = *(const float4*)(g_agg + mr*128 + c4);
            sb[i] = *(const uint4*)(Wt + r*256 + c4);
        }
    }

    for(int ch = 0; ch < 8; ch++){
        #pragma unroll
        for(int i = 0; i < 4; i++){
            int s = tid + i*256;
            int r = s >> 3, c4 = (s & 7)*4;
            uint32_t* d = As + r*36 + c4;
            d[0] = f2tf(sa[i].x); d[1] = f2tf(sa[i].y); d[2] = f2tf(sa[i].z); d[3] = f2tf(sa[i].w);
            *(uint4*)(Bs + r*36 + c4) = sb[i];
        }
        __syncthreads();
        if(ch + 1 < 8){
            int nc = ch + 1;
            const float* Ap = (nc < 4) ? g_agg : g_h;
            int kc = (nc & 3)*32;
            #pragma unroll
            for(int i = 0; i < 4; i++){
                int s = tid + i*256;
                int r = s >> 3, c4 = (s & 7)*4;
                int mr = m0 + r; if(mr >= N_NODES) mr = N_NODES-1;
                sa[i] = *(const float4*)(Ap + mr*128 + kc + c4);
                sb[i] = *(const uint4*)(Wt + r*256 + nc*32 + c4);
            }
        }
        const uint32_t* a_sm = As + (wy*32 + g)*36 + t;
        const uint32_t* b_sm = Bs + (wx*64 + g)*36 + t;
        #pragma unroll
        for(int kk = 0; kk < 4; kk++){
            int k0 = kk*8;
            uint32_t a[2][4];
            #pragma unroll
            for(int mi = 0; mi < 2; mi++){
                const uint32_t* p = a_sm + mi*16*36 + k0;
                a[mi][0] = p[0]; a[mi][1] = p[8*36]; a[mi][2] = p[4]; a[mi][3] = p[8*36+4];
            }
            #pragma unroll
            for(int nf = 0; nf < 8; nf++){
                const uint32_t* q = b_sm + nf*8*36 + k0;
                uint32_t b0 = q[0], b1 = q[4];
                mma_tf32(c[0][nf], a[0], b0, b1);
                mma_tf32(c[1][nf], a[1], b0, b1);
            }
        }
        __syncthreads();
    }

    int colb = wx*64;
    #pragma unroll
    for(int mi = 0; mi < 2; mi++)
        #pragma unroll
        for(int rr = 0; rr < 2; rr++){
            float s = 0.f, sq = 0.f;
            #pragma unroll
            for(int nf = 0; nf < 8; nf++)
                #pragma unroll
                for(int j = 0; j < 2; j++){
                    int col = colb + nf*8 + 2*t + j;
                    float v = c[mi][nf][rr*2+j] + prm[col];
                    c[mi][nf][rr*2+j] = v;
                    s += v; sq += v*v;
                }
            s  += __shfl_xor_sync(0xffffffffu, s, 1);
            s  += __shfl_xor_sync(0xffffffffu, s, 2);
            sq += __shfl_xor_sync(0xffffffffu, sq, 1);
            sq += __shfl_xor_sync(0xffffffffu, sq, 2);
            if(t == 0){
                int row = wy*32 + mi*16 + rr*8 + g;
                ps[wx*128 + row] = s;
                pq[wx*128 + row] = sq;
            }
        }
    __syncthreads();
    #pragma unroll
    for(int mi = 0; mi < 2; mi++)
        #pragma unroll
        for(int rr = 0; rr < 2; rr++){
            int row = wy*32 + mi*16 + rr*8 + g;
            int m = m0 + row;
            float st  = ps[row] + ps[128+row];
            float sqt = pq[row] + pq[128+row];
            float mu  = st * (1.0f/128.0f);
            float var = sqt * (1.0f/128.0f) - mu*mu;
            float rs  = rsqrtf(var + 1e-5f);
            #pragma unroll
            for(int nf = 0; nf < 8; nf++){
                int col = colb + nf*8 + 2*t;
                float2 o;
                o.x = fmaxf((c[mi][nf][rr*2+0]-mu)*rs*prm[128+col]   + prm[256+col],   0.f);
                o.y = fmaxf((c[mi][nf][rr*2+1]-mu)*rs*prm[128+col+1] + prm[256+col+1], 0.f);
                if(m < N_NODES) *(float2*)(g_h + m*128 + col) = o;
                if(FUSE){
                    Hs[row*132 + col]   = f2tf(o.x);
                    Hs[row*132 + col+1] = f2tf(o.y);
                }
            }
        }

    if(FUSE){
        __syncthreads();
        #pragma unroll
        for(int sl = 0; sl < 2; sl++){
            const uint32_t* W = g_W1s + sl*16384;
            #pragma unroll
            for(int mi = 0; mi < 2; mi++)
                #pragma unroll
                for(int nf = 0; nf < 8; nf++)
                    #pragma unroll
                    for(int j = 0; j < 4; j++) c[mi][nf][j] = 0.f;

            uint4 sb2[4];
            #pragma unroll
            for(int i = 0; i < 4; i++){
                int s = tid + i*256;
                int r = s >> 3, c4 = (s & 7)*4;
                sb2[i] = *(const uint4*)(W + r*128 + c4);
            }
            for(int ch = 0; ch < 4; ch++){
                #pragma unroll
                for(int i = 0; i < 4; i++){
                    int s = tid + i*256;
                    int r = s >> 3, c4 = (s & 7)*4;
                    *(uint4*)(Bs + r*36 + c4) = sb2[i];
                }
                __syncthreads();
                if(ch + 1 < 4){
                    int nc = ch + 1;
                    #pragma unroll
                    for(int i = 0; i < 4; i++){
                        int s = tid + i*256;
                        int r = s >> 3, c4 = (s & 7)*4;
                        sb2[i] = *(const uint4*)(W + r*128 + nc*32 + c4);
                    }
                }
                const uint32_t* a_sm = Hs + (wy*32 + g)*132 + ch*32 + t;
                const uint32_t* b_sm = Bs + (wx*64 + g)*36 + t;
                #pragma unroll
                for(int kk = 0; kk < 4; kk++){
                    int k0 = kk*8;
                    uint32_t a[2][4];
                    #pragma unroll
                    for(int mi = 0; mi < 2; mi++){
                        const uint32_t* p = a_sm + mi*16*132 + k0;
                        a[mi][0] = p[0]; a[mi][1] = p[8*132]; a[mi][2] = p[4]; a[mi][3] = p[8*132+4];
                    }
                    #pragma unroll
                    for(int nf = 0; nf < 8; nf++){
                        const uint32_t* q = b_sm + nf*8*36 + k0;
                        uint32_t b0 = q[0], b1 = q[4];
                        mma_tf32(c[0][nf], a[0], b0, b1);
                        mma_tf32(c[1][nf], a[1], b0, b1);
                    }
                }
                __syncthreads();
            }
            float* out = sl ? g_Bn : g_An;
            #pragma unroll
            for(int mi = 0; mi < 2; mi++)
                #pragma unroll
                for(int rr = 0; rr < 2; rr++){
                    int row = wy*32 + mi*16 + rr*8 + g;
                    int m = m0 + row;
                    if(m < N_NODES){
                        #pragma unroll
                        for(int nf = 0; nf < 8; nf++){
                            int col = colb + nf*8 + 2*t;
                            *(float2*)(out + m*128 + col) =
                                make_float2(c[mi][nf][rr*2+0], c[mi][nf][rr*2+1]);
                        }
                    }
                }
        }
    }
}

// ---------------- edge head: CSR-order, warp-pipelined, 4x16 register-blocked phase 1 ----------------
#define EG 4
#define EPB (128*EG)
#define EH_H1_STRIDE 132
#define EH_W2_STRIDE 72
#define EH_F_H1   0
#define EH_F_W2   (EH_F_H1 + 128*EH_H1_STRIDE)
#define EH_F_W1C  (EH_F_W2 + 128*EH_W2_STRIDE)
#define EH_F_B1   (EH_F_W1C + 8*128)
#define EH_F_B2   (EH_F_B1 + 128)
#define EH_F_W3   (EH_F_B2 + 64)
#define EH_F_EAS  (EH_F_W3 + 64)          // [8 warps][128] floats
#define EH_F_IDS  (EH_F_EAS + 8*128)      // [8 warps][48] ints (eid|src|dst x16)
#define EH_F_END  (EH_F_IDS + 8*48)
#define EH_SMEM_BYTES (EH_F_END*4 + 64)

__global__ void __launch_bounds__(256) edge_k(
        const float* __restrict__ ea,
        const float* __restrict__ b1, const float* __restrict__ b2,
        const float* __restrict__ W3, const float* __restrict__ b3,
        float* __restrict__ out){
    extern __shared__ float smf[];
    float* H1  = smf + EH_F_H1;
    float* W2s = smf + EH_F_W2;
    float* W1c = smf + EH_F_W1C;
    float* b1s = smf + EH_F_B1;
    float* b2s = smf + EH_F_B2;
    float* W3s = smf + EH_F_W3;

    int tid = threadIdx.x, lane = tid & 31, wid = tid >> 5;
    float* eaS = smf + EH_F_EAS + wid*128;
    int*   idS = (int*)(smf + EH_F_IDS) + wid*48;   // eid[16] | src[16] | dst[16]

    if(tid < 128) b1s[tid] = b1[tid];
    else if(tid < 192) b2s[tid-128] = b2[tid-128];
    else               W3s[tid-192] = W3[tid-192];
    {
        int idx = tid*4;
        *reinterpret_cast<float4*>(&W1c[idx]) =
            *reinterpret_cast<const float4*>(&g_W1c[idx]);
    }
    {
        uint32_t* W2u = (uint32_t*)W2s;
        #pragma unroll
        for(int r = 0; r < 8; r++){
            int idx = r*1024 + tid*4;
            int k = idx >> 6, n = idx & 63;
            uint4 v = *reinterpret_cast<const uint4*>(&g_W2u[idx]);
            *(uint4*)(W2u + k*EH_W2_STRIDE + n) = v;
        }
    }
    __syncthreads();

    float bias3 = b3[0];
    uint32_t* H1w = (uint32_t*)(H1 + wid*16*EH_H1_STRIDE);
    int g = lane >> 2, t = lane & 3;
    const uint32_t* W2u = (const uint32_t*)W2s;
    const uint32_t* b_sm = W2u + t*EH_W2_STRIDE + g;

    for(int grp = 0; grp < EG; grp++){
        int e0 = blockIdx.x*EPB + grp*128 + wid*16;   // CSR position base
        if(e0 >= N_EDGES) break;

        // ---- stage per-warp row metadata + ea ----
        if(lane < 16){
            int p = e0 + lane;
            int eid = __ldg(g_csrE + p);
            idS[lane]      = eid;
            idS[16 + lane] = __ldg(g_csr  + p);
            idS[32 + lane] = __ldg(g_csrD + p);
            float4 ev0 = *reinterpret_cast<const float4*>(ea + eid*8);
            float4 ev1 = *reinterpret_cast<const float4*>(ea + eid*8 + 4);
            *(float4*)(eaS + lane*8)     = ev0;
            *(float4*)(eaS + lane*8 + 4) = ev1;
        }
        __syncwarp();

        // ---- phase 1: 4 rows x 16 cols per thread ----
        {
            int rg = lane >> 3, cg = lane & 7;
            int n0 = cg*16;
            float e8r[4][8];
            int src4[4], dst4[4];
            #pragma unroll
            for(int r4 = 0; r4 < 4; r4++){
                int row = rg*4 + r4;
                float4 u0 = *(float4*)(eaS + row*8);
                float4 u1 = *(float4*)(eaS + row*8 + 4);
                e8r[r4][0]=u0.x; e8r[r4][1]=u0.y; e8r[r4][2]=u0.z; e8r[r4][3]=u0.w;
                e8r[r4][4]=u1.x; e8r[r4][5]=u1.y; e8r[r4][6]=u1.z; e8r[r4][7]=u1.w;
                src4[r4] = idS[16 + row];
                dst4[r4] = idS[32 + row];
            }
            #pragma unroll
            for(int jj = 0; jj < 4; jj++){
                int ch = ((cg >> 1) + jj) & 3;
                int c0 = n0 + ch*4;
                float4 w[8];
                #pragma unroll
                for(int k = 0; k < 8; k++)
                    w[k] = *reinterpret_cast<const float4*>(&W1c[k*HID + c0]);
                float4 bb = *reinterpret_cast<const float4*>(&b1s[c0]);
                #pragma unroll
                for(int r4 = 0; r4 < 4; r4++){
                    int row = rg*4 + r4;
                    float4 a = *reinterpret_cast<const float4*>(g_An + src4[r4]*HID + c0);
                    float4 b = *reinterpret_cast<const float4*>(g_Bn + dst4[r4]*HID + c0);
                    float vx = a.x + b.x + bb.x;
                    float vy = a.y + b.y + bb.y;
                    float vz = a.z + b.z + bb.z;
                    float vw = a.w + b.w + bb.w;
                    #pragma unroll
                    for(int k = 0; k < 8; k++){
                        vx += e8r[r4][k]*w[k].x; vy += e8r[r4][k]*w[k].y;
                        vz += e8r[r4][k]*w[k].z; vw += e8r[r4][k]*w[k].w;
                    }
                    uint4 o;
                    o.x = f2tf(fmaxf(vx,0.f)); o.y = f2tf(fmaxf(vy,0.f));
                    o.z = f2tf(fmaxf(vz,0.f)); o.w = f2tf(fmaxf(vw,0.f));
                    *(uint4*)(H1w + row*EH_H1_STRIDE + c0) = o;
                }
            }
        }
        __syncwarp();

        // ---- phase 2: [16 x 64] = H1 @ W2t ; relu(+b2).W3 + b3 ----
        float c2[8][4];
        #pragma unroll
        for(int nf = 0; nf < 8; nf++)
            #pragma unroll
            for(int j = 0; j < 4; j++) c2[nf][j] = 0.f;

        const uint32_t* a_sm = H1w + g*EH_H1_STRIDE + t;
        #pragma unroll
        for(int kk = 0; kk < 16; kk++){
            int k0 = kk*8;
            uint32_t a[4];
            const uint32_t* p = a_sm + k0;
            a[0] = p[0]; a[1] = p[8*EH_H1_STRIDE]; a[2] = p[4]; a[3] = p[8*EH_H1_STRIDE+4];
            const uint32_t* q = b_sm + k0*EH_W2_STRIDE;
            #pragma unroll
            for(int nf = 0; nf < 8; nf++){
                uint32_t b0 = q[nf*8];
                uint32_t b1v = q[4*EH_W2_STRIDE + nf*8];
                mma_tf32(c2[nf], a, b0, b1v);
            }
        }

        #pragma unroll
        for(int rr = 0; rr < 2; rr++){
            float p = 0.f;
            #pragma unroll
            for(int nf = 0; nf < 8; nf++)
                #pragma unroll
                for(int j = 0; j < 2; j++){
                    int col = nf*8 + 2*t + j;
                    p += fmaxf(c2[nf][rr*2+j] + b2s[col], 0.f) * W3s[col];
                }
            p += __shfl_xor_sync(0xffffffffu, p, 1);
            p += __shfl_xor_sync(0xffffffffu, p, 2);
            if(t == 0) out[idS[rr*8 + g]] = p + bias3;
        }
        __syncwarp();
    }
}

// ---------------- launch ----------------
extern "C" void kernel_launch(void* const* d_in, const int* in_sizes, int n_in,
                              void* d_out, int out_size){
    const float* x   = (const float*)d_in[0];
    const int*   ei  = (const int*)  d_in[1];
    const float* ea  = (const float*)d_in[2];
    const float* Win = (const float*)d_in[3];
    const float* bin = (const float*)d_in[4];
    const float* Wl  = (const float*)d_in[5];
    const float* bl  = (const float*)d_in[6];
    const float* Wr  = (const float*)d_in[7];
    const float* lng = (const float*)d_in[8];
    const float* lnb = (const float*)d_in[9];
    const float* W1  = (const float*)d_in[10];
    const float* b1  = (const float*)d_in[11];
    const float* W2  = (const float*)d_in[12];
    const float* b2  = (const float*)d_in[13];
    const float* W3  = (const float*)d_in[14];
    const float* b3  = (const float*)d_in[15];
    const int* src = ei;
    const int* dst = ei + N_EDGES;

    static bool attr_done = false;
    if(!attr_done){
        cudaFuncSetAttribute(gemm_layer<1>, cudaFuncAttributeMaxDynamicSharedMemorySize, GL_SMEM1);
        cudaFuncSetAttribute(edge_k, cudaFuncAttributeMaxDynamicSharedMemorySize, EH_SMEM_BYTES);
        attr_done = true;
    }

    prep_hist_inproj_k<<<PB + EB + NB, 256>>>(dst, x, Win, bin, W1, W2, Wl, Wr);
    scan_k<<<1, 1024>>>();
    fill_k<<<(N_EDGES+255)/256, 256>>>(src, dst);

    const int gb = (N_NODES + 127)/128;  // 391
    uint32_t* Wt0; cudaGetSymbolAddress((void**)&Wt0, g_Wt);
    for(int l = 0; l < 4; l++){
        agg_k<<<(N_NODES+7)/8, 256>>>();
        if(l < 3)
            gemm_layer<0><<<gb, 256, GL_SMEM0>>>(Wt0 + l*HID*256,
                                                 bl + l*HID, lng + l*HID, lnb + l*HID);
        else
            gemm_layer<1><<<gb, 256, GL_SMEM1>>>(Wt0 + l*HID*256,
                                                 bl + l*HID, lng + l*HID, lnb + l*HID);
    }

    edge_k<<<(N_EDGES + EPB - 1)/EPB, 256, EH_SMEM_BYTES>>>(ea, b1, b2, W3, b3, (float*)d_out);
}

// round 15
// speedup vs baseline: 1.0539x; 1.0092x over previous
#include <cuda_runtime.h>
#include <cstdint>

#define N_NODES 50000
#define N_EDGES 800000
#define HID 128

// ---------------- scratch ----------------
__device__ float    g_h  [N_NODES*HID];
__device__ float    g_agg[N_NODES*HID];
__device__ float    g_An [N_NODES*HID];
__device__ float    g_Bn [N_NODES*HID];
__device__ int      g_cntfill[2*N_NODES];      // [cnt | fill]
__device__ int      g_rowptr[N_NODES+1];
__device__ int      g_csr [N_EDGES];           // src per CSR position
__device__ int      g_csrE[N_EDGES];           // original edge id per CSR position
__device__ int      g_csrD[N_EDGES];           // dst per CSR position
__device__ uint32_t g_Wt [4*HID*256];          // tf32 [l][n][k] combined Wl|Wr
__device__ uint32_t g_W1s[2*HID*HID];          // tf32 [slice][n][k] from W1
__device__ uint32_t g_W2u[HID*64];             // tf32 [k][c] W2 transposed
__device__ float    g_W1c[8*HID];              // fp32 W1 cols 256..263 transposed

// ---------------- tf32 mma helpers ----------------
__device__ __forceinline__ uint32_t f2tf(float f){
    uint32_t r;
    asm("cvt.rna.tf32.f32 %0, %1;" : "=r"(r) : "f"(f));
    return r;
}
__device__ __forceinline__ void mma_tf32(float* c, const uint32_t* a, uint32_t b0, uint32_t b1){
    asm volatile("mma.sync.aligned.m16n8k8.row.col.f32.tf32.tf32.f32 "
        "{%0,%1,%2,%3}, {%4,%5,%6,%7}, {%8,%9}, {%0,%1,%2,%3};"
        : "+f"(c[0]), "+f"(c[1]), "+f"(c[2]), "+f"(c[3])
        : "r"(a[0]), "r"(a[1]), "r"(a[2]), "r"(a[3]), "r"(b0), "r"(b1));
}

// ---------------- combo: weight prep + hist + input projection ----------------
#define PB 512                           // prep blocks (4*128*256/256)
#define EB ((N_EDGES+255)/256)           // 3125
#define NB ((N_NODES+1)/2)               // 25000

__global__ void prep_hist_inproj_k(const int* __restrict__ dst, const float* __restrict__ x,
                                   const float* __restrict__ Win, const float* __restrict__ bin,
                                   const float* __restrict__ W1, const float* __restrict__ W2,
                                   const float* __restrict__ Wl, const float* __restrict__ Wr){
    if(blockIdx.x < PB){
        int i = blockIdx.x*256 + threadIdx.x;
        if(i < 4*HID*256){
            int l = i >> 15; int r = i & 32767; int n = r >> 8, k = r & 255;
            float v = (k < 128) ? Wl[l*16384 + n*128 + k] : Wr[l*16384 + n*128 + (k-128)];
            g_Wt[i] = f2tf(v);
        }
        if(i < 2*HID*HID){
            int s = i >> 14; int r = i & 16383; int n = r >> 7, k = r & 127;
            g_W1s[i] = f2tf(W1[n*264 + s*128 + k]);
        }
        if(i < HID*64){ int k = i/64, c = i%64; g_W2u[i] = f2tf(W2[c*HID + k]); }
        if(i < 8*HID) { int k = i/HID, c = i%HID; g_W1c[i] = W1[c*264 + 256 + k]; }
        return;
    }
    if(blockIdx.x < PB + EB){
        int i = (blockIdx.x - PB)*256 + threadIdx.x;
        if(i < N_EDGES) atomicAdd(&g_cntfill[dst[i]], 1);
        return;
    }
    __shared__ float xs[2][16];
    int tid = threadIdx.x;
    int n0 = (blockIdx.x - PB - EB)*2;
    if(tid < 32){
        int nn = tid/16, k = tid%16;
        int n = n0 + nn;
        xs[nn][k] = (n < N_NODES) ? x[n*16 + k] : 0.f;
    }
    __syncthreads();
    int nn = tid/HID, c = tid%HID;
    int n = n0 + nn;
    if(n < N_NODES){
        float acc = bin[c];
        const float* w = Win + c*16;
        #pragma unroll
        for(int k = 0; k < 16; k++) acc += xs[nn][k]*w[k];
        g_h[n*HID + c] = acc;
    }
}

// ---------------- fast scan ----------------
#define SCH 49   // ceil(50000/1024)

__global__ void scan_k(){
    __shared__ int ssum[1024];
    int tid = threadIdx.x;
    int base = tid*SCH;
    int v[SCH];
    int tot = 0;
    #pragma unroll
    for(int j = 0; j < SCH; j++){
        int i = base + j;
        v[j] = (i < N_NODES) ? g_cntfill[i] : 0;
        tot += v[j];
    }
    ssum[tid] = tot;
    __syncthreads();
    for(int off = 1; off < 1024; off <<= 1){
        int t = (tid >= off) ? ssum[tid-off] : 0;
        __syncthreads();
        ssum[tid] += t;
        __syncthreads();
    }
    int run = ssum[tid] - tot;
    #pragma unroll
    for(int j = 0; j < SCH; j++){
        int i = base + j;
        if(i < N_NODES) g_rowptr[i] = run;
        run += v[j];
    }
    if(tid == 1023) g_rowptr[N_NODES] = run;
}

__global__ void fill_k(const int* __restrict__ src, const int* __restrict__ dst){
    int i = blockIdx.x*blockDim.x + threadIdx.x;
    if(i < N_EDGES){
        int d = dst[i];
        int pos = g_rowptr[d] + atomicAdd(&g_cntfill[N_NODES + d], 1);
        g_csr [pos] = src[i];
        g_csrE[pos] = i;
        g_csrD[pos] = d;
    }
}

// ---------------- mean aggregation (CSR gather, MLP=4) + cntfill re-zero ----------------
__global__ void agg_k(){
    int z = blockIdx.x*blockDim.x + threadIdx.x;
    if(z < 2*N_NODES) g_cntfill[z] = 0;

    int warp = threadIdx.x >> 5, lane = threadIdx.x & 31;
    int n = blockIdx.x*8 + warp;
    if(n >= N_NODES) return;
    int beg = g_rowptr[n], end = g_rowptr[n+1];
    float4 acc = make_float4(0.f,0.f,0.f,0.f);
    const float4* hp = reinterpret_cast<const float4*>(g_h);
    int j = beg;
    for(; j + 4 <= end; j += 4){
        int s0 = g_csr[j], s1 = g_csr[j+1], s2 = g_csr[j+2], s3 = g_csr[j+3];
        float4 v0 = hp[s0*32 + lane];
        float4 v1 = hp[s1*32 + lane];
        float4 v2 = hp[s2*32 + lane];
        float4 v3 = hp[s3*32 + lane];
        acc.x += (v0.x+v1.x) + (v2.x+v3.x);
        acc.y += (v0.y+v1.y) + (v2.y+v3.y);
        acc.z += (v0.z+v1.z) + (v2.z+v3.z);
        acc.w += (v0.w+v1.w) + (v2.w+v3.w);
    }
    for(; j < end; j++){
        int s = g_csr[j];
        float4 v = hp[s*32 + lane];
        acc.x += v.x; acc.y += v.y; acc.z += v.z; acc.w += v.w;
    }
    float inv = (end > beg) ? 1.0f/(float)(end - beg) : 0.0f;
    acc.x *= inv; acc.y *= inv; acc.z *= inv; acc.w *= inv;
    reinterpret_cast<float4*>(g_agg)[n*32 + lane] = acc;
}

// ---------------- layer GEMM (K=256, single-buffer) + bias/LN/ReLU; FUSE=1 emits An/Bn ----------------
#define GL_AS   0
#define GL_BS   (128*36)
#define GL_PRM  (GL_BS + 128*36)
#define GL_PS   (GL_PRM + 384)
#define GL_PQ   (GL_PS + 256)
#define GL_HS   (GL_PQ + 256)
#define GL_SMEM0 (GL_HS*4)
#define GL_SMEM1 ((GL_HS + 128*132)*4)

template<int FUSE>
__global__ void __launch_bounds__(256) gemm_layer(
        const uint32_t* __restrict__ Wt,
        const float* __restrict__ bias, const float* __restrict__ lng,
        const float* __restrict__ lnb){
    extern __shared__ uint32_t smu[];
    uint32_t* As = smu + GL_AS;
    uint32_t* Bs = smu + GL_BS;
    float* prm = (float*)(smu + GL_PRM);
    float* ps  = (float*)(smu + GL_PS);
    float* pq  = (float*)(smu + GL_PQ);
    uint32_t* Hs = smu + GL_HS;

    int tid = threadIdx.x;
    int lane = tid & 31, wid = tid >> 5;
    int g = lane >> 2, t = lane & 3;
    int wy = wid & 3, wx = wid >> 2;
    int m0 = blockIdx.x*128;

    float c[2][8][4];
    #pragma unroll
    for(int mi = 0; mi < 2; mi++)
        #pragma unroll
        for(int nf = 0; nf < 8; nf++)
            #pragma unroll
            for(int j = 0; j < 4; j++) c[mi][nf][j] = 0.f;

    if(tid < 128){
        prm[tid] = bias[tid]; prm[128+tid] = lng[tid]; prm[256+tid] = lnb[tid];
    }

    float4 sa[4]; uint4 sb[4];
    {
        #pragma unroll
        for(int i = 0; i < 4; i++){
            int s = tid + i*256;
            int r = s >> 3, c4 = (s & 7)*4;
            int mr = m0 + r; if(mr >= N_NODES) mr = N_NODES-1;
            sa[i] = *(const float4*)(g_agg + mr*128 + c4);
            sb[i] = *(const uint4*)(Wt + r*256 + c4);
        }
    }

    for(int ch = 0; ch < 8; ch++){
        #pragma unroll
        for(int i = 0; i < 4; i++){
            int s = tid + i*256;
            int r = s >> 3, c4 = (s & 7)*4;
            uint32_t* d = As + r*36 + c4;
            d[0] = f2tf(sa[i].x); d[1] = f2tf(sa[i].y); d[2] = f2tf(sa[i].z); d[3] = f2tf(sa[i].w);
            *(uint4*)(Bs + r*36 + c4) = sb[i];
        }
        __syncthreads();
        if(ch + 1 < 8){
            int nc = ch + 1;
            const float* Ap = (nc < 4) ? g_agg : g_h;
            int kc = (nc & 3)*32;
            #pragma unroll
            for(int i = 0; i < 4; i++){
                int s = tid + i*256;
                int r = s >> 3, c4 = (s & 7)*4;
                int mr = m0 + r; if(mr >= N_NODES) mr = N_NODES-1;
                sa[i] = *(const float4*)(Ap + mr*128 + kc + c4);
                sb[i] = *(const uint4*)(Wt + r*256 + nc*32 + c4);
            }
        }
        const uint32_t* a_sm = As + (wy*32 + g)*36 + t;
        const uint32_t* b_sm = Bs + (wx*64 + g)*36 + t;
        #pragma unroll
        for(int kk = 0; kk < 4; kk++){
            int k0 = kk*8;
            uint32_t a[2][4];
            #pragma unroll
            for(int mi = 0; mi < 2; mi++){
                const uint32_t* p = a_sm + mi*16*36 + k0;
                a[mi][0] = p[0]; a[mi][1] = p[8*36]; a[mi][2] = p[4]; a[mi][3] = p[8*36+4];
            }
            #pragma unroll
            for(int nf = 0; nf < 8; nf++){
                const uint32_t* q = b_sm + nf*8*36 + k0;
                uint32_t b0 = q[0], b1 = q[4];
                mma_tf32(c[0][nf], a[0], b0, b1);
                mma_tf32(c[1][nf], a[1], b0, b1);
            }
        }
        __syncthreads();
    }

    int colb = wx*64;
    #pragma unroll
    for(int mi = 0; mi < 2; mi++)
        #pragma unroll
        for(int rr = 0; rr < 2; rr++){
            float s = 0.f, sq = 0.f;
            #pragma unroll
            for(int nf = 0; nf < 8; nf++)
                #pragma unroll
                for(int j = 0; j < 2; j++){
                    int col = colb + nf*8 + 2*t + j;
                    float v = c[mi][nf][rr*2+j] + prm[col];
                    c[mi][nf][rr*2+j] = v;
                    s += v; sq += v*v;
                }
            s  += __shfl_xor_sync(0xffffffffu, s, 1);
            s  += __shfl_xor_sync(0xffffffffu, s, 2);
            sq += __shfl_xor_sync(0xffffffffu, sq, 1);
            sq += __shfl_xor_sync(0xffffffffu, sq, 2);
            if(t == 0){
                int row = wy*32 + mi*16 + rr*8 + g;
                ps[wx*128 + row] = s;
                pq[wx*128 + row] = sq;
            }
        }
    __syncthreads();
    #pragma unroll
    for(int mi = 0; mi < 2; mi++)
        #pragma unroll
        for(int rr = 0; rr < 2; rr++){
            int row = wy*32 + mi*16 + rr*8 + g;
            int m = m0 + row;
            float st  = ps[row] + ps[128+row];
            float sqt = pq[row] + pq[128+row];
            float mu  = st * (1.0f/128.0f);
            float var = sqt * (1.0f/128.0f) - mu*mu;
            float rs  = rsqrtf(var + 1e-5f);
            #pragma unroll
            for(int nf = 0; nf < 8; nf++){
                int col = colb + nf*8 + 2*t;
                float2 o;
                o.x = fmaxf((c[mi][nf][rr*2+0]-mu)*rs*prm[128+col]   + prm[256+col],   0.f);
                o.y = fmaxf((c[mi][nf][rr*2+1]-mu)*rs*prm[128+col+1] + prm[256+col+1], 0.f);
                if(m < N_NODES) *(float2*)(g_h + m*128 + col) = o;
                if(FUSE){
                    Hs[row*132 + col]   = f2tf(o.x);
                    Hs[row*132 + col+1] = f2tf(o.y);
                }
            }
        }

    if(FUSE){
        __syncthreads();
        #pragma unroll
        for(int sl = 0; sl < 2; sl++){
            const uint32_t* W = g_W1s + sl*16384;
            #pragma unroll
            for(int mi = 0; mi < 2; mi++)
                #pragma unroll
                for(int nf = 0; nf < 8; nf++)
                    #pragma unroll
                    for(int j = 0; j < 4; j++) c[mi][nf][j] = 0.f;

            uint4 sb2[4];
            #pragma unroll
            for(int i = 0; i < 4; i++){
                int s = tid + i*256;
                int r = s >> 3, c4 = (s & 7)*4;
                sb2[i] = *(const uint4*)(W + r*128 + c4);
            }
            for(int ch = 0; ch < 4; ch++){
                #pragma unroll
                for(int i = 0; i < 4; i++){
                    int s = tid + i*256;
                    int r = s >> 3, c4 = (s & 7)*4;
                    *(uint4*)(Bs + r*36 + c4) = sb2[i];
                }
                __syncthreads();
                if(ch + 1 < 4){
                    int nc = ch + 1;
                    #pragma unroll
                    for(int i = 0; i < 4; i++){
                        int s = tid + i*256;
                        int r = s >> 3, c4 = (s & 7)*4;
                        sb2[i] = *(const uint4*)(W + r*128 + nc*32 + c4);
                    }
                }
                const uint32_t* a_sm = Hs + (wy*32 + g)*132 + ch*32 + t;
                const uint32_t* b_sm = Bs + (wx*64 + g)*36 + t;
                #pragma unroll
                for(int kk = 0; kk < 4; kk++){
                    int k0 = kk*8;
                    uint32_t a[2][4];
                    #pragma unroll
                    for(int mi = 0; mi < 2; mi++){
                        const uint32_t* p = a_sm + mi*16*132 + k0;
                        a[mi][0] = p[0]; a[mi][1] = p[8*132]; a[mi][2] = p[4]; a[mi][3] = p[8*132+4];
                    }
                    #pragma unroll
                    for(int nf = 0; nf < 8; nf++){
                        const uint32_t* q = b_sm + nf*8*36 + k0;
                        uint32_t b0 = q[0], b1 = q[4];
                        mma_tf32(c[0][nf], a[0], b0, b1);
                        mma_tf32(c[1][nf], a[1], b0, b1);
                    }
                }
                __syncthreads();
            }
            float* out = sl ? g_Bn : g_An;
            #pragma unroll
            for(int mi = 0; mi < 2; mi++)
                #pragma unroll
                for(int rr = 0; rr < 2; rr++){
                    int row = wy*32 + mi*16 + rr*8 + g;
                    int m = m0 + row;
                    if(m < N_NODES){
                        #pragma unroll
                        for(int nf = 0; nf < 8; nf++){
                            int col = colb + nf*8 + 2*t;
                            *(float2*)(out + m*128 + col) =
                                make_float2(c[mi][nf][rr*2+0], c[mi][nf][rr*2+1]);
                        }
                    }
                }
        }
    }
}

// ---------------- edge head: CSR-order, warp-pipelined, 4x16 register-blocked phase 1 ----------------
#define EG 4
#define EPB (128*EG)
#define EH_H1_STRIDE 132
#define EH_W2_STRIDE 72
#define EH_F_H1   0
#define EH_F_W2   (EH_F_H1 + 128*EH_H1_STRIDE)
#define EH_F_W1C  (EH_F_W2 + 128*EH_W2_STRIDE)
#define EH_F_B1   (EH_F_W1C + 8*128)
#define EH_F_B2   (EH_F_B1 + 128)
#define EH_F_W3   (EH_F_B2 + 64)
#define EH_F_EAS  (EH_F_W3 + 64)          // [8 warps][128] floats
#define EH_F_IDS  (EH_F_EAS + 8*128)      // [8 warps][48] ints (eid|src|dst x16)
#define EH_F_END  (EH_F_IDS + 8*48)
#define EH_SMEM_BYTES (EH_F_END*4 + 64)

__global__ void __launch_bounds__(256) edge_k(
        const float* __restrict__ ea,
        const float* __restrict__ b1, const float* __restrict__ b2,
        const float* __restrict__ W3, const float* __restrict__ b3,
        float* __restrict__ out){
    extern __shared__ float smf[];
    float* H1  = smf + EH_F_H1;
    float* W2s = smf + EH_F_W2;
    float* W1c = smf + EH_F_W1C;
    float* b1s = smf + EH_F_B1;
    float* b2s = smf + EH_F_B2;
    float* W3s = smf + EH_F_W3;

    int tid = threadIdx.x, lane = tid & 31, wid = tid >> 5;
    float* eaS = smf + EH_F_EAS + wid*128;
    int*   idS = (int*)(smf + EH_F_IDS) + wid*48;   // eid[16] | src[16] | dst[16]

    if(tid < 128) b1s[tid] = b1[tid];
    else if(tid < 192) b2s[tid-128] = b2[tid-128];
    else               W3s[tid-192] = W3[tid-192];
    {
        int idx = tid*4;
        *reinterpret_cast<float4*>(&W1c[idx]) =
            *reinterpret_cast<const float4*>(&g_W1c[idx]);
    }
    {
        uint32_t* W2u = (uint32_t*)W2s;
        #pragma unroll
        for(int r = 0; r < 8; r++){
            int idx = r*1024 + tid*4;
            int k = idx >> 6, n = idx & 63;
            uint4 v = *reinterpret_cast<const uint4*>(&g_W2u[idx]);
            *(uint4*)(W2u + k*EH_W2_STRIDE + n) = v;
        }
    }
    __syncthreads();

    float bias3 = b3[0];
    uint32_t* H1w = (uint32_t*)(H1 + wid*16*EH_H1_STRIDE);
    int g = lane >> 2, t = lane & 3;
    const uint32_t* W2u = (const uint32_t*)W2s;
    const uint32_t* b_sm = W2u + t*EH_W2_STRIDE + g;

    for(int grp = 0; grp < EG; grp++){
        int e0 = blockIdx.x*EPB + grp*128 + wid*16;   // CSR position base
        if(e0 >= N_EDGES) break;

        // ---- stage per-warp row metadata + ea ----
        if(lane < 16){
            int p = e0 + lane;
            int eid = __ldg(g_csrE + p);
            idS[lane]      = eid;
            idS[16 + lane] = __ldg(g_csr  + p);
            idS[32 + lane] = __ldg(g_csrD + p);
            float4 ev0 = *reinterpret_cast<const float4*>(ea + eid*8);
            float4 ev1 = *reinterpret_cast<const float4*>(ea + eid*8 + 4);
            *(float4*)(eaS + lane*8)     = ev0;
            *(float4*)(eaS + lane*8 + 4) = ev1;
        }
        __syncwarp();

        // ---- phase 1: 4 rows x 16 cols per thread ----
        {
            int rg = lane >> 3, cg = lane & 7;
            int n0 = cg*16;
            float e8r[4][8];
            int src4[4], dst4[4];
            #pragma unroll
            for(int r4 = 0; r4 < 4; r4++){
                int row = rg*4 + r4;
                float4 u0 = *(float4*)(eaS + row*8);
                float4 u1 = *(float4*)(eaS + row*8 + 4);
                e8r[r4][0]=u0.x; e8r[r4][1]=u0.y; e8r[r4][2]=u0.z; e8r[r4][3]=u0.w;
                e8r[r4][4]=u1.x; e8r[r4][5]=u1.y; e8r[r4][6]=u1.z; e8r[r4][7]=u1.w;
                src4[r4] = idS[16 + row];
                dst4[r4] = idS[32 + row];
            }
            #pragma unroll
            for(int jj = 0; jj < 4; jj++){
                int ch = ((cg >> 1) + jj) & 3;
                int c0 = n0 + ch*4;
                float4 w[8];
                #pragma unroll
                for(int k = 0; k < 8; k++)
                    w[k] = *reinterpret_cast<const float4*>(&W1c[k*HID + c0]);
                float4 bb = *reinterpret_cast<const float4*>(&b1s[c0]);
                #pragma unroll
                for(int r4 = 0; r4 < 4; r4++){
                    int row = rg*4 + r4;
                    float4 a = *reinterpret_cast<const float4*>(g_An + src4[r4]*HID + c0);
                    float4 b = *reinterpret_cast<const float4*>(g_Bn + dst4[r4]*HID + c0);
                    float vx = a.x + b.x + bb.x;
                    float vy = a.y + b.y + bb.y;
                    float vz = a.z + b.z + bb.z;
                    float vw = a.w + b.w + bb.w;
                    #pragma unroll
                    for(int k = 0; k < 8; k++){
                        vx += e8r[r4][k]*w[k].x; vy += e8r[r4][k]*w[k].y;
                        vz += e8r[r4][k]*w[k].z; vw += e8r[r4][k]*w[k].w;
                    }
                    uint4 o;
                    o.x = f2tf(fmaxf(vx,0.f)); o.y = f2tf(fmaxf(vy,0.f));
                    o.z = f2tf(fmaxf(vz,0.f)); o.w = f2tf(fmaxf(vw,0.f));
                    *(uint4*)(H1w + row*EH_H1_STRIDE + c0) = o;
                }
            }
        }
        __syncwarp();

        // ---- phase 2: [16 x 64] = H1 @ W2t ; relu(+b2).W3 + b3 ----
        float c2[8][4];
        #pragma unroll
        for(int nf = 0; nf < 8; nf++)
            #pragma unroll
            for(int j = 0; j < 4; j++) c2[nf][j] = 0.f;

        const uint32_t* a_sm = H1w + g*EH_H1_STRIDE + t;
        #pragma unroll
        for(int kk = 0; kk < 16; kk++){
            int k0 = kk*8;
            uint32_t a[4];
            const uint32_t* p = a_sm + k0;
            a[0] = p[0]; a[1] = p[8*EH_H1_STRIDE]; a[2] = p[4]; a[3] = p[8*EH_H1_STRIDE+4];
            const uint32_t* q = b_sm + k0*EH_W2_STRIDE;
            #pragma unroll
            for(int nf = 0; nf < 8; nf++){
                uint32_t b0 = q[nf*8];
                uint32_t b1v = q[4*EH_W2_STRIDE + nf*8];
                mma_tf32(c2[nf], a, b0, b1v);
            }
        }

        #pragma unroll
        for(int rr = 0; rr < 2; rr++){
            float p = 0.f;
            #pragma unroll
            for(int nf = 0; nf < 8; nf++)
                #pragma unroll
                for(int j = 0; j < 2; j++){
                    int col = nf*8 + 2*t + j;
                    p += fmaxf(c2[nf][rr*2+j] + b2s[col], 0.f) * W3s[col];
                }
            p += __shfl_xor_sync(0xffffffffu, p, 1);
            p += __shfl_xor_sync(0xffffffffu, p, 2);
            if(t == 0) out[idS[rr*8 + g]] = p + bias3;
        }
        __syncwarp();
    }
}

// ---------------- launch ----------------
extern "C" void kernel_launch(void* const* d_in, const int* in_sizes, int n_in,
                              void* d_out, int out_size){
    const float* x   = (const float*)d_in[0];
    const int*   ei  = (const int*)  d_in[1];
    const float* ea  = (const float*)d_in[2];
    const float* Win = (const float*)d_in[3];
    const float* bin = (const float*)d_in[4];
    const float* Wl  = (const float*)d_in[5];
    const float* bl  = (const float*)d_in[6];
    const float* Wr  = (const float*)d_in[7];
    const float* lng = (const float*)d_in[8];
    const float* lnb = (const float*)d_in[9];
    const float* W1  = (const float*)d_in[10];
    const float* b1  = (const float*)d_in[11];
    const float* W2  = (const float*)d_in[12];
    const float* b2  = (const float*)d_in[13];
    const float* W3  = (const float*)d_in[14];
    const float* b3  = (const float*)d_in[15];
    const int* src = ei;
    const int* dst = ei + N_EDGES;

    static bool attr_done = false;
    if(!attr_done){
        cudaFuncSetAttribute(gemm_layer<1>, cudaFuncAttributeMaxDynamicSharedMemorySize, GL_SMEM1);
        cudaFuncSetAttribute(edge_k, cudaFuncAttributeMaxDynamicSharedMemorySize, EH_SMEM_BYTES);
        attr_done = true;
    }

    prep_hist_inproj_k<<<PB + EB + NB, 256>>>(dst, x, Win, bin, W1, W2, Wl, Wr);
    scan_k<<<1, 1024>>>();
    fill_k<<<(N_EDGES+255)/256, 256>>>(src, dst);

    const int gb = (N_NODES + 127)/128;  // 391
    uint32_t* Wt0; cudaGetSymbolAddress((void**)&Wt0, g_Wt);
    for(int l = 0; l < 4; l++){
        agg_k<<<(N_NODES+7)/8, 256>>>();
        if(l < 3)
            gemm_layer<0><<<gb, 256, GL_SMEM0>>>(Wt0 + l*HID*256,
                                                 bl + l*HID, lng + l*HID, lnb + l*HID);
        else
            gemm_layer<1><<<gb, 256, GL_SMEM1>>>(Wt0 + l*HID*256,
                                                 bl + l*HID, lng + l*HID, lnb + l*HID);
    }

    edge_k<<<(N_EDGES + EPB - 1)/EPB, 256, EH_SMEM_BYTES>>>(ea, b1, b2, W3, b3, (float*)d_out);
}